// round 1
// baseline (speedup 1.0000x reference)
#include <cuda_runtime.h>
#include <cuda_bf16.h>
#include <cstdint>

// Problem constants
// x:      [16, 4096, 384]  (B, N, C), N = 64*64 token grid
// W_qkv:  [384, 1152]
// b_qkv:  [1152]
// W_proj: [384, 384]
// out:    [16, 4096, 384] fp32
//
// Window attention: 8x8 windows over the 64x64 grid -> 64 windows/batch,
// 1024 windows total, 64 tokens per window, 12 heads, head_dim=32.

#define TOKENS   65536      // 16*4096
#define C_DIM    384
#define QKV_DIM  1152

// Scratch (allocation-free rule: __device__ globals)
__device__ float g_qkv[(size_t)TOKENS * QKV_DIM];   // 302 MB
__device__ float g_attn[(size_t)TOKENS * C_DIM];    // 100 MB

// ---------------------------------------------------------------------------
// Classic fp32 SGEMM: C[M,N] = A[M,K] @ B[K,N] (+ bias[N])
// Block tile 128x128, K-tile 16, 256 threads, 8x8 accumulators/thread.
// All dims assumed divisible (holds for M=65536, N in {1152,384}, K=384).
// ---------------------------------------------------------------------------
#define BM 128
#define BN 128
#define BK 16
#define TM 8
#define TN 8

__global__ __launch_bounds__(256)
void sgemm_kernel(const float* __restrict__ A, const float* __restrict__ B,
                  const float* __restrict__ bias, float* __restrict__ C,
                  int M, int N, int K)
{
    __shared__ float As[BK][BM];   // transposed A tile
    __shared__ float Bs[BK][BN];

    const int tid = threadIdx.x;
    const int tx = tid & 15;       // 0..15 -> N direction
    const int ty = tid >> 4;       // 0..15 -> M direction
    const int bx = blockIdx.x;     // N tile
    const int by = blockIdx.y;     // M tile

    const float* Aptr = A + (size_t)by * BM * K;
    const float* Bptr = B + (size_t)bx * BN;

    float acc[TM][TN];
    #pragma unroll
    for (int i = 0; i < TM; i++)
        #pragma unroll
        for (int j = 0; j < TN; j++)
            acc[i][j] = 0.0f;

    for (int k0 = 0; k0 < K; k0 += BK) {
        // Load A tile: 128 rows x 16 cols = 512 float4, 2 per thread.
        #pragma unroll
        for (int i = 0; i < 2; i++) {
            int f = tid * 2 + i;
            int r  = f >> 2;          // 0..127
            int c4 = f & 3;           // 0..3 (float4 within 16 cols)
            float4 v = *(const float4*)(Aptr + (size_t)r * K + k0 + c4 * 4);
            As[c4 * 4 + 0][r] = v.x;
            As[c4 * 4 + 1][r] = v.y;
            As[c4 * 4 + 2][r] = v.z;
            As[c4 * 4 + 3][r] = v.w;
        }
        // Load B tile: 16 rows x 128 cols = 512 float4, 2 per thread.
        #pragma unroll
        for (int i = 0; i < 2; i++) {
            int f = tid * 2 + i;
            int r  = f >> 5;          // 0..15
            int c4 = f & 31;          // 0..31
            float4 v = *(const float4*)(Bptr + (size_t)(k0 + r) * N + c4 * 4);
            *(float4*)&Bs[r][c4 * 4] = v;
        }
        __syncthreads();

        #pragma unroll
        for (int k = 0; k < BK; k++) {
            float ra[TM], rb[TN];
            #pragma unroll
            for (int i = 0; i < TM; i++) ra[i] = As[k][ty * TM + i];
            #pragma unroll
            for (int j = 0; j < TN; j++) rb[j] = Bs[k][tx * TN + j];
            #pragma unroll
            for (int i = 0; i < TM; i++)
                #pragma unroll
                for (int j = 0; j < TN; j++)
                    acc[i][j] += ra[i] * rb[j];
        }
        __syncthreads();
    }

    // Epilogue: add bias, vectorized stores.
    const int col0 = bx * BN + tx * TN;
    float bb[TN];
    if (bias) {
        #pragma unroll
        for (int j = 0; j < TN; j++) bb[j] = bias[col0 + j];
    } else {
        #pragma unroll
        for (int j = 0; j < TN; j++) bb[j] = 0.0f;
    }

    #pragma unroll
    for (int i = 0; i < TM; i++) {
        int row = by * BM + ty * TM + i;
        float4 o0, o1;
        o0.x = acc[i][0] + bb[0]; o0.y = acc[i][1] + bb[1];
        o0.z = acc[i][2] + bb[2]; o0.w = acc[i][3] + bb[3];
        o1.x = acc[i][4] + bb[4]; o1.y = acc[i][5] + bb[5];
        o1.z = acc[i][6] + bb[6]; o1.w = acc[i][7] + bb[7];
        float* cp = C + (size_t)row * N + col0;
        *(float4*)(cp)     = o0;
        *(float4*)(cp + 4) = o1;
    }
}

// ---------------------------------------------------------------------------
// Per-(window, head) attention. Grid (1024 windows, 12 heads), 256 threads.
// qkv row layout (1152): [q heads 0..11 | k heads 0..11 | v heads 0..11],
// each head 32 floats. Token for window (wh,wc), slot r (0..63):
//   n = (wh*8 + r/8)*64 + wc*8 + (r%8)
// ---------------------------------------------------------------------------
__global__ __launch_bounds__(256)
void attn_kernel(const float* __restrict__ qkv, float* __restrict__ attn_out)
{
    __shared__ float sq[64][32];
    __shared__ float sk[64][32];
    __shared__ float sv[64][32];
    __shared__ float ss[64][64];

    const int wx   = blockIdx.x;   // 0..1023
    const int head = blockIdx.y;   // 0..11
    const int b  = wx >> 6;
    const int wi = wx & 63;
    const int wh = wi >> 3;
    const int wc = wi & 7;
    const int tid = threadIdx.x;

    // Load q,k,v: each 64x32 = 512 float4; 2 float4 per thread per matrix.
    #pragma unroll
    for (int i = 0; i < 2; i++) {
        int f  = tid * 2 + i;
        int r  = f >> 3;          // token slot 0..63
        int c4 = f & 7;           // float4 within 32
        int n = ((wh * 8 + (r >> 3)) << 6) + wc * 8 + (r & 7);
        const float* row = qkv + (size_t)(b * 4096 + n) * QKV_DIM + head * 32;
        *(float4*)&sq[r][c4 * 4] = *(const float4*)(row + c4 * 4);
        *(float4*)&sk[r][c4 * 4] = *(const float4*)(row + 384 + c4 * 4);
        *(float4*)&sv[r][c4 * 4] = *(const float4*)(row + 768 + c4 * 4);
    }
    __syncthreads();

    // Scores S[qr][kr] = scale * q.k   (4096 entries, 16 per thread)
    const float scale = 0.17677669529663687f;  // 1/sqrt(32)
    for (int e = tid; e < 4096; e += 256) {
        int qr = e >> 6, kr = e & 63;
        float s = 0.0f;
        #pragma unroll
        for (int d = 0; d < 32; d++) s += sq[qr][d] * sk[kr][d];
        ss[qr][kr] = s * scale;
    }
    __syncthreads();

    // Row softmax (64 rows; one thread per row)
    if (tid < 64) {
        float m = -1e30f;
        #pragma unroll 8
        for (int j = 0; j < 64; j++) m = fmaxf(m, ss[tid][j]);
        float sum = 0.0f;
        #pragma unroll 8
        for (int j = 0; j < 64; j++) {
            float e = __expf(ss[tid][j] - m);
            ss[tid][j] = e;
            sum += e;
        }
        float inv = 1.0f / sum;
        #pragma unroll 8
        for (int j = 0; j < 64; j++) ss[tid][j] *= inv;
    }
    __syncthreads();

    // O = S @ V : 64x32 outputs, 8 per thread, write straight to token order.
    for (int e = tid; e < 2048; e += 256) {
        int r = e >> 5, d = e & 31;
        float o = 0.0f;
        #pragma unroll
        for (int k = 0; k < 64; k++) o += ss[r][k] * sv[k][d];
        int n = ((wh * 8 + (r >> 3)) << 6) + wc * 8 + (r & 7);
        attn_out[(size_t)(b * 4096 + n) * C_DIM + head * 32 + d] = o;
    }
}

// ---------------------------------------------------------------------------
// Host launcher
// ---------------------------------------------------------------------------
extern "C" void kernel_launch(void* const* d_in, const int* in_sizes, int n_in,
                              void* d_out, int out_size)
{
    const float* x      = (const float*)d_in[0];   // [65536, 384]
    const float* W_qkv  = (const float*)d_in[1];   // [384, 1152]
    const float* b_qkv  = (const float*)d_in[2];   // [1152]
    const float* W_proj = (const float*)d_in[3];   // [384, 384]
    float* out = (float*)d_out;                    // [65536, 384]

    float *qkv, *attn;
    cudaGetSymbolAddress((void**)&qkv, g_qkv);
    cudaGetSymbolAddress((void**)&attn, g_attn);

    // 1) QKV projection: [65536,384] @ [384,1152] + bias
    {
        dim3 grid(QKV_DIM / BN, TOKENS / BM);
        sgemm_kernel<<<grid, 256>>>(x, W_qkv, b_qkv, qkv, TOKENS, QKV_DIM, C_DIM);
    }
    // 2) Windowed attention
    {
        dim3 grid(1024, 12);
        attn_kernel<<<grid, 256>>>(qkv, attn);
    }
    // 3) Output projection: [65536,384] @ [384,384]
    {
        dim3 grid(C_DIM / BN, TOKENS / BM);
        sgemm_kernel<<<grid, 256>>>(attn, W_proj, nullptr, out, TOKENS, C_DIM, C_DIM);
    }
}

// round 2
// speedup vs baseline: 2.4275x; 2.4275x over previous
#include <cuda_runtime.h>
#include <cuda_bf16.h>
#include <cstdint>

// x:      [16, 4096, 384] fp32 -> out [16,4096,384] fp32
// Window attention: 8x8 windows over 64x64 grid, 12 heads, hd=32.

#define TOKENS   65536
#define C_DIM    384
#define QKV_DIM  1152

// Scratch (__device__ globals per allocation-free rule)
__device__ float          g_qkv[(size_t)TOKENS * QKV_DIM];     // 302 MB
__device__ __nv_bfloat16  g_xh [(size_t)TOKENS * C_DIM];
__device__ __nv_bfloat16  g_xl [(size_t)TOKENS * C_DIM];
__device__ __nv_bfloat16  g_ah [(size_t)TOKENS * C_DIM];       // attn out hi
__device__ __nv_bfloat16  g_al [(size_t)TOKENS * C_DIM];       // attn out lo
__device__ __nv_bfloat16  g_wqh[(size_t)C_DIM * QKV_DIM];
__device__ __nv_bfloat16  g_wql[(size_t)C_DIM * QKV_DIM];
__device__ __nv_bfloat16  g_wph[(size_t)C_DIM * C_DIM];
__device__ __nv_bfloat16  g_wpl[(size_t)C_DIM * C_DIM];

static __device__ __forceinline__ uint32_t smem_u32(const void* p) {
    return (uint32_t)__cvta_generic_to_shared(p);
}

// ---------------------------------------------------------------------------
// fp32 -> (hi, lo) bf16 split.  v = hi + lo + O(2^-17 |v|)
// ---------------------------------------------------------------------------
__global__ void split_kernel(const float* __restrict__ in,
                             __nv_bfloat16* __restrict__ hi,
                             __nv_bfloat16* __restrict__ lo, int n4)
{
    int i = blockIdx.x * blockDim.x + threadIdx.x;
    if (i >= n4) return;
    float4 v = ((const float4*)in)[i];
    __nv_bfloat16 h0 = __float2bfloat16(v.x);
    __nv_bfloat16 h1 = __float2bfloat16(v.y);
    __nv_bfloat16 h2 = __float2bfloat16(v.z);
    __nv_bfloat16 h3 = __float2bfloat16(v.w);
    __nv_bfloat16 l0 = __float2bfloat16(v.x - __bfloat162float(h0));
    __nv_bfloat16 l1 = __float2bfloat16(v.y - __bfloat162float(h1));
    __nv_bfloat16 l2 = __float2bfloat16(v.z - __bfloat162float(h2));
    __nv_bfloat16 l3 = __float2bfloat16(v.w - __bfloat162float(h3));
    __nv_bfloat162* hp = (__nv_bfloat162*)hi;
    __nv_bfloat162* lp = (__nv_bfloat162*)lo;
    hp[i*2]   = __nv_bfloat162(h0, h1);
    hp[i*2+1] = __nv_bfloat162(h2, h3);
    lp[i*2]   = __nv_bfloat162(l0, l1);
    lp[i*2+1] = __nv_bfloat162(l2, l3);
}

// ---------------------------------------------------------------------------
// 3x-bf16-split GEMM on tensor cores (mma.sync m16n8k16).
// C[M,N] = Ah@Bh + Ah@Bl + Al@Bh (+bias).  CTA 128x128, BK=32, 256 thr.
// 8 warps as 2(M) x 4(N); warp tile 64x32.
// ---------------------------------------------------------------------------
#define MMA_BF16(d, a, b)                                                      \
    asm volatile(                                                              \
        "mma.sync.aligned.m16n8k16.row.col.f32.bf16.bf16.f32 "                 \
        "{%0,%1,%2,%3},{%4,%5,%6,%7},{%8,%9},{%0,%1,%2,%3};"                   \
        : "+f"(d[0]), "+f"(d[1]), "+f"(d[2]), "+f"(d[3])                       \
        : "r"(a[0]), "r"(a[1]), "r"(a[2]), "r"(a[3]), "r"(b[0]), "r"(b[1]))

__global__ __launch_bounds__(256, 2)
void gemm3_kernel(const __nv_bfloat16* __restrict__ Ah,
                  const __nv_bfloat16* __restrict__ Al,
                  const __nv_bfloat16* __restrict__ Bh,
                  const __nv_bfloat16* __restrict__ Bl,
                  const float* __restrict__ bias,
                  float* __restrict__ C, int N, int K)
{
    __shared__ __nv_bfloat16 sAh[128][40];   // 80B row stride: ldmatrix conflict-free
    __shared__ __nv_bfloat16 sAl[128][40];
    __shared__ __nv_bfloat16 sBh[32][136];   // 272B row stride
    __shared__ __nv_bfloat16 sBl[32][136];

    const int tid  = threadIdx.x;
    const int lane = tid & 31;
    const int warp = tid >> 5;
    const int wm   = warp >> 2;      // 0..1
    const int wn   = warp & 3;       // 0..3
    const int m0   = blockIdx.y * 128;
    const int n0   = blockIdx.x * 128;

    float acc[4][4][4];
    #pragma unroll
    for (int mi = 0; mi < 4; mi++)
        #pragma unroll
        for (int ni = 0; ni < 4; ni++)
            #pragma unroll
            for (int c = 0; c < 4; c++) acc[mi][ni][c] = 0.0f;

    for (int k0 = 0; k0 < K; k0 += 32) {
        // --- A tiles: 128x32 bf16 each (hi, lo); 512 16B-chunks / buffer ---
        #pragma unroll
        for (int i = 0; i < 2; i++) {
            int f = tid * 2 + i;
            int r = f >> 2, c16 = f & 3;
            size_t go = (size_t)(m0 + r) * K + k0 + c16 * 8;
            uint4 vh = *(const uint4*)(Ah + go);
            uint4 vl = *(const uint4*)(Al + go);
            *(uint2*)&sAh[r][c16*8]     = make_uint2(vh.x, vh.y);
            *(uint2*)&sAh[r][c16*8 + 4] = make_uint2(vh.z, vh.w);
            *(uint2*)&sAl[r][c16*8]     = make_uint2(vl.x, vl.y);
            *(uint2*)&sAl[r][c16*8 + 4] = make_uint2(vl.z, vl.w);
        }
        // --- B tiles: 32x128 bf16 each ---
        #pragma unroll
        for (int i = 0; i < 2; i++) {
            int f = tid * 2 + i;
            int r = f >> 4, c16 = f & 15;
            size_t go = (size_t)(k0 + r) * N + n0 + c16 * 8;
            *(uint4*)&sBh[r][c16*8] = *(const uint4*)(Bh + go);
            *(uint4*)&sBl[r][c16*8] = *(const uint4*)(Bl + go);
        }
        __syncthreads();

        #pragma unroll
        for (int kh = 0; kh < 2; kh++) {
            // B fragments: 4 n-tiles x (hi, lo)
            uint32_t bh[4][2], bl[4][2];
            int brow = kh * 16 + (lane & 15);
            #pragma unroll
            for (int ni = 0; ni < 4; ni++) {
                uint32_t ad = smem_u32(&sBh[brow][wn * 32 + ni * 8]);
                asm volatile("ldmatrix.sync.aligned.m8n8.x2.trans.shared.b16 {%0,%1},[%2];"
                             : "=r"(bh[ni][0]), "=r"(bh[ni][1]) : "r"(ad));
                ad = smem_u32(&sBl[brow][wn * 32 + ni * 8]);
                asm volatile("ldmatrix.sync.aligned.m8n8.x2.trans.shared.b16 {%0,%1},[%2];"
                             : "=r"(bl[ni][0]), "=r"(bl[ni][1]) : "r"(ad));
            }
            #pragma unroll
            for (int mi = 0; mi < 4; mi++) {
                int arow = wm * 64 + mi * 16 + ((lane >> 3) & 1) * 8 + (lane & 7);
                int acol = kh * 16 + (lane >> 4) * 8;
                uint32_t Ahf[4], Alf[4];
                uint32_t ad = smem_u32(&sAh[arow][acol]);
                asm volatile("ldmatrix.sync.aligned.m8n8.x4.shared.b16 {%0,%1,%2,%3},[%4];"
                             : "=r"(Ahf[0]), "=r"(Ahf[1]), "=r"(Ahf[2]), "=r"(Ahf[3]) : "r"(ad));
                ad = smem_u32(&sAl[arow][acol]);
                asm volatile("ldmatrix.sync.aligned.m8n8.x4.shared.b16 {%0,%1,%2,%3},[%4];"
                             : "=r"(Alf[0]), "=r"(Alf[1]), "=r"(Alf[2]), "=r"(Alf[3]) : "r"(ad));
                #pragma unroll
                for (int ni = 0; ni < 4; ni++) {
                    MMA_BF16(acc[mi][ni], Ahf, bh[ni]);
                    MMA_BF16(acc[mi][ni], Ahf, bl[ni]);
                    MMA_BF16(acc[mi][ni], Alf, bh[ni]);
                }
            }
        }
        __syncthreads();
    }

    // Epilogue: C fragment -> global (float2 stores), + bias
    const int rbase = m0 + wm * 64 + (lane >> 2);
    const int cbase = n0 + wn * 32 + (lane & 3) * 2;
    #pragma unroll
    for (int ni = 0; ni < 4; ni++) {
        int c = cbase + ni * 8;
        float b0 = 0.f, b1 = 0.f;
        if (bias) { b0 = bias[c]; b1 = bias[c + 1]; }
        #pragma unroll
        for (int mi = 0; mi < 4; mi++) {
            int r = rbase + mi * 16;
            float2 v0 = make_float2(acc[mi][ni][0] + b0, acc[mi][ni][1] + b1);
            float2 v1 = make_float2(acc[mi][ni][2] + b0, acc[mi][ni][3] + b1);
            *(float2*)(C + (size_t)r * N + c)       = v0;
            *(float2*)(C + (size_t)(r + 8) * N + c) = v1;
        }
    }
}

// ---------------------------------------------------------------------------
// Per-(window, head) attention. Grid (1024, 12), 256 threads.
// Emits hi/lo bf16 split of output directly (feeds proj GEMM).
// ---------------------------------------------------------------------------
__global__ __launch_bounds__(256)
void attn_kernel(const float* __restrict__ qkv,
                 __nv_bfloat16* __restrict__ oh,
                 __nv_bfloat16* __restrict__ ol)
{
    __shared__ float sq[64][36];
    __shared__ float sk[64][36];
    __shared__ float sv[64][36];
    __shared__ float ss[64][68];

    const int wx   = blockIdx.x;
    const int head = blockIdx.y;
    const int b  = wx >> 6;
    const int wi = wx & 63;
    const int wh = wi >> 3;
    const int wc = wi & 7;
    const int tid = threadIdx.x;

    // Load q,k,v (64x32 each): 512 float4 per matrix, 2 per thread.
    #pragma unroll
    for (int i = 0; i < 2; i++) {
        int f  = tid * 2 + i;
        int r  = f >> 3;
        int c4 = f & 7;
        int n = ((wh * 8 + (r >> 3)) << 6) + wc * 8 + (r & 7);
        const float* row = qkv + (size_t)(b * 4096 + n) * QKV_DIM + head * 32;
        *(float4*)&sq[r][c4 * 4] = *(const float4*)(row + c4 * 4);
        *(float4*)&sk[r][c4 * 4] = *(const float4*)(row + 384 + c4 * 4);
        *(float4*)&sv[r][c4 * 4] = *(const float4*)(row + 768 + c4 * 4);
    }
    __syncthreads();

    // QK^T, 4x4 register-blocked: thread -> scores[qr0..+3][kr0..+3]
    {
        const float scale = 0.17677669529663687f;  // 1/sqrt(32)
        int qr0 = (tid >> 4) * 4;
        int kr0 = (tid & 15) * 4;
        float a[4][4];
        #pragma unroll
        for (int i = 0; i < 4; i++)
            #pragma unroll
            for (int j = 0; j < 4; j++) a[i][j] = 0.0f;
        #pragma unroll
        for (int d = 0; d < 32; d += 4) {
            float4 qv[4], kv[4];
            #pragma unroll
            for (int i = 0; i < 4; i++) qv[i] = *(float4*)&sq[qr0 + i][d];
            #pragma unroll
            for (int j = 0; j < 4; j++) kv[j] = *(float4*)&sk[kr0 + j][d];
            #pragma unroll
            for (int i = 0; i < 4; i++)
                #pragma unroll
                for (int j = 0; j < 4; j++)
                    a[i][j] += qv[i].x * kv[j].x + qv[i].y * kv[j].y +
                               qv[i].z * kv[j].z + qv[i].w * kv[j].w;
        }
        #pragma unroll
        for (int i = 0; i < 4; i++)
            *(float4*)&ss[qr0 + i][kr0] = make_float4(
                a[i][0] * scale, a[i][1] * scale, a[i][2] * scale, a[i][3] * scale);
    }
    __syncthreads();

    // Softmax: 4 threads per row (shuffle-combine within groups of 4 lanes).
    {
        int row  = tid >> 2;
        int part = (tid & 3) * 16;
        float m = -1e30f;
        #pragma unroll
        for (int j = 0; j < 16; j++) m = fmaxf(m, ss[row][part + j]);
        m = fmaxf(m, __shfl_xor_sync(0xffffffffu, m, 1));
        m = fmaxf(m, __shfl_xor_sync(0xffffffffu, m, 2));
        float sum = 0.0f;
        #pragma unroll
        for (int j = 0; j < 16; j++) {
            float e = __expf(ss[row][part + j] - m);
            ss[row][part + j] = e;
            sum += e;
        }
        sum += __shfl_xor_sync(0xffffffffu, sum, 1);
        sum += __shfl_xor_sync(0xffffffffu, sum, 2);
        float inv = 1.0f / sum;
        #pragma unroll
        for (int j = 0; j < 16; j++) ss[row][part + j] *= inv;
    }
    __syncthreads();

    // O = S @ V : thread handles 2 rows x 4 dims. Write hi/lo bf16 split.
    {
        int r0 = (tid >> 3) * 2;
        int d0 = (tid & 7) * 4;
        float4 o0 = make_float4(0.f, 0.f, 0.f, 0.f);
        float4 o1 = make_float4(0.f, 0.f, 0.f, 0.f);
        #pragma unroll 8
        for (int k = 0; k < 64; k++) {
            float s0 = ss[r0][k], s1 = ss[r0 + 1][k];
            float4 v = *(float4*)&sv[k][d0];
            o0.x += s0 * v.x; o0.y += s0 * v.y; o0.z += s0 * v.z; o0.w += s0 * v.w;
            o1.x += s1 * v.x; o1.y += s1 * v.y; o1.z += s1 * v.z; o1.w += s1 * v.w;
        }
        #pragma unroll
        for (int rr = 0; rr < 2; rr++) {
            float4 o = rr ? o1 : o0;
            int r = r0 + rr;
            int n = ((wh * 8 + (r >> 3)) << 6) + wc * 8 + (r & 7);
            size_t base = (size_t)(b * 4096 + n) * C_DIM + head * 32 + d0;
            __nv_bfloat16 h0 = __float2bfloat16(o.x);
            __nv_bfloat16 h1 = __float2bfloat16(o.y);
            __nv_bfloat16 h2 = __float2bfloat16(o.z);
            __nv_bfloat16 h3 = __float2bfloat16(o.w);
            __nv_bfloat16 l0 = __float2bfloat16(o.x - __bfloat162float(h0));
            __nv_bfloat16 l1 = __float2bfloat16(o.y - __bfloat162float(h1));
            __nv_bfloat16 l2 = __float2bfloat16(o.z - __bfloat162float(h2));
            __nv_bfloat16 l3 = __float2bfloat16(o.w - __bfloat162float(h3));
            *(__nv_bfloat162*)(oh + base)     = __nv_bfloat162(h0, h1);
            *(__nv_bfloat162*)(oh + base + 2) = __nv_bfloat162(h2, h3);
            *(__nv_bfloat162*)(ol + base)     = __nv_bfloat162(l0, l1);
            *(__nv_bfloat162*)(ol + base + 2) = __nv_bfloat162(l2, l3);
        }
    }
}

// ---------------------------------------------------------------------------
// Host launcher
// ---------------------------------------------------------------------------
extern "C" void kernel_launch(void* const* d_in, const int* in_sizes, int n_in,
                              void* d_out, int out_size)
{
    const float* x      = (const float*)d_in[0];
    const float* W_qkv  = (const float*)d_in[1];
    const float* b_qkv  = (const float*)d_in[2];
    const float* W_proj = (const float*)d_in[3];
    float* out = (float*)d_out;

    float *qkv;
    __nv_bfloat16 *xh, *xl, *ah, *al, *wqh, *wql, *wph, *wpl;
    cudaGetSymbolAddress((void**)&qkv, g_qkv);
    cudaGetSymbolAddress((void**)&xh,  g_xh);
    cudaGetSymbolAddress((void**)&xl,  g_xl);
    cudaGetSymbolAddress((void**)&ah,  g_ah);
    cudaGetSymbolAddress((void**)&al,  g_al);
    cudaGetSymbolAddress((void**)&wqh, g_wqh);
    cudaGetSymbolAddress((void**)&wql, g_wql);
    cudaGetSymbolAddress((void**)&wph, g_wph);
    cudaGetSymbolAddress((void**)&wpl, g_wpl);

    // Splits
    {
        int n4 = TOKENS * C_DIM / 4;
        split_kernel<<<(n4 + 255) / 256, 256>>>(x, xh, xl, n4);
        int w4 = C_DIM * QKV_DIM / 4;
        split_kernel<<<(w4 + 255) / 256, 256>>>(W_qkv, wqh, wql, w4);
        int p4 = C_DIM * C_DIM / 4;
        split_kernel<<<(p4 + 255) / 256, 256>>>(W_proj, wph, wpl, p4);
    }
    // 1) QKV projection (tensor cores, 3x split)
    {
        dim3 grid(QKV_DIM / 128, TOKENS / 128);
        gemm3_kernel<<<grid, 256>>>(xh, xl, wqh, wql, b_qkv, qkv, QKV_DIM, C_DIM);
    }
    // 2) Windowed attention (emits hi/lo split)
    {
        dim3 grid(1024, 12);
        attn_kernel<<<grid, 256>>>(qkv, ah, al);
    }
    // 3) Output projection (tensor cores, 3x split)
    {
        dim3 grid(C_DIM / 128, TOKENS / 128);
        gemm3_kernel<<<grid, 256>>>(ah, al, wph, wpl, nullptr, out, C_DIM, C_DIM);
    }
}

// round 4
// speedup vs baseline: 2.9125x; 1.1998x over previous
#include <cuda_runtime.h>
#include <cuda_bf16.h>
#include <cstdint>

// x: [16,4096,384] fp32 -> out [16,4096,384] fp32
// 8x8 window attention over 64x64 grid, 12 heads, hd=32.

#define TOKENS   65536
#define C_DIM    384
#define QKV_DIM  1152

__device__ float          g_qkv[(size_t)TOKENS * QKV_DIM];
__device__ __nv_bfloat16  g_xh [(size_t)TOKENS * C_DIM];
__device__ __nv_bfloat16  g_xl [(size_t)TOKENS * C_DIM];
__device__ __nv_bfloat16  g_ah [(size_t)TOKENS * C_DIM];
__device__ __nv_bfloat16  g_al [(size_t)TOKENS * C_DIM];
__device__ __nv_bfloat16  g_wqh[(size_t)C_DIM * QKV_DIM];
__device__ __nv_bfloat16  g_wql[(size_t)C_DIM * QKV_DIM];
__device__ __nv_bfloat16  g_wph[(size_t)C_DIM * C_DIM];
__device__ __nv_bfloat16  g_wpl[(size_t)C_DIM * C_DIM];

static __device__ __forceinline__ uint32_t smem_u32(const void* p) {
    return (uint32_t)__cvta_generic_to_shared(p);
}

#define CP_ASYNC16(smem, gptr) \
    asm volatile("cp.async.cg.shared.global [%0], [%1], 16;" :: "r"(smem), "l"(gptr))
#define CP_COMMIT() asm volatile("cp.async.commit_group;" ::: "memory")

#define MMA_BF16(d, a, b)                                                      \
    asm volatile(                                                              \
        "mma.sync.aligned.m16n8k16.row.col.f32.bf16.bf16.f32 "                 \
        "{%0,%1,%2,%3},{%4,%5,%6,%7},{%8,%9},{%0,%1,%2,%3};"                   \
        : "+f"(d[0]), "+f"(d[1]), "+f"(d[2]), "+f"(d[3])                       \
        : "r"(a[0]), "r"(a[1]), "r"(a[2]), "r"(a[3]), "r"(b[0]), "r"(b[1]))

// ---------------------------------------------------------------------------
// fp32 -> (hi, lo) bf16 split
// ---------------------------------------------------------------------------
__global__ void split_kernel(const float* __restrict__ in,
                             __nv_bfloat16* __restrict__ hi,
                             __nv_bfloat16* __restrict__ lo, int n4)
{
    int i = blockIdx.x * blockDim.x + threadIdx.x;
    if (i >= n4) return;
    float4 v = ((const float4*)in)[i];
    __nv_bfloat16 h0 = __float2bfloat16(v.x), h1 = __float2bfloat16(v.y);
    __nv_bfloat16 h2 = __float2bfloat16(v.z), h3 = __float2bfloat16(v.w);
    __nv_bfloat162* hp = (__nv_bfloat162*)hi;
    __nv_bfloat162* lp = (__nv_bfloat162*)lo;
    hp[i*2]   = __nv_bfloat162(h0, h1);
    hp[i*2+1] = __nv_bfloat162(h2, h3);
    lp[i*2]   = __nv_bfloat162(__float2bfloat16(v.x - __bfloat162float(h0)),
                               __float2bfloat16(v.y - __bfloat162float(h1)));
    lp[i*2+1] = __nv_bfloat162(__float2bfloat16(v.z - __bfloat162float(h2)),
                               __float2bfloat16(v.w - __bfloat162float(h3)));
}

// ---------------------------------------------------------------------------
// 3x-bf16-split GEMM (mma.sync m16n8k16), cp.async double-buffered.
// C[M,N] = Ah@Bh + Ah@Bl + Al@Bh (+bias). A [M][K], B [K][N] bf16 hi/lo.
// CTA 128x128, 4 warps (2x2), warp tile 64x64, BK=32, 2 smem stages.
// ---------------------------------------------------------------------------
// smem arena per stage (bytes, bf16 elems padded):
//   sAh 128x40 @0        (5120 elems, 10240B)
//   sAl 128x40 @10240
//   sBh  32x136 @20480   (4352 elems, 8704B)
//   sBl  32x136 @29184
//   stage stride 37888
#define ST_AL 10240
#define ST_BH 20480
#define ST_BL 29184
#define ST_SZ 37888
#define GEMM_DYNSMEM (2 * ST_SZ)

__global__ __launch_bounds__(128, 2)
void gemm3_kernel(const __nv_bfloat16* __restrict__ Ah,
                  const __nv_bfloat16* __restrict__ Al,
                  const __nv_bfloat16* __restrict__ Bh,
                  const __nv_bfloat16* __restrict__ Bl,
                  const float* __restrict__ bias,
                  float* __restrict__ C, int N, int K)
{
    extern __shared__ char smem_raw[];
    const uint32_t sbase = smem_u32(smem_raw);

    const int tid  = threadIdx.x;
    const int lane = tid & 31;
    const int warp = tid >> 5;
    const int wm   = warp >> 1;     // 0..1
    const int wn   = warp & 1;      // 0..1
    const int m0   = blockIdx.y * 128;
    const int n0   = blockIdx.x * 128;
    const int KT   = K / 32;

    float acc[4][8][4];
    #pragma unroll
    for (int mi = 0; mi < 4; mi++)
        #pragma unroll
        for (int ni = 0; ni < 8; ni++)
            #pragma unroll
            for (int c = 0; c < 4; c++) acc[mi][ni][c] = 0.0f;

    // Per-thread cp.async offsets
    // A: 512 chunks (128 rows x 4 chunks of 8 elems); 4 per thread
    uint32_t aso[4]; size_t ago[4];
    // B: 512 chunks (32 rows x 16 chunks); 4 per thread
    uint32_t bso[4]; size_t bgo[4];
    #pragma unroll
    for (int j = 0; j < 4; j++) {
        int idx = j * 128 + tid;
        int ar = idx >> 2, ac = idx & 3;
        aso[j] = (uint32_t)(ar * 80 + ac * 16);
        ago[j] = (size_t)ar * K + ac * 8;
        int br = idx >> 4, bc = idx & 15;
        bso[j] = (uint32_t)(br * 272 + bc * 16);
        bgo[j] = (size_t)br * N + bc * 8;
    }

    auto load_stage = [&](int kt, int st) {
        uint32_t b = sbase + st * ST_SZ;
        const __nv_bfloat16* pah = Ah + (size_t)m0 * K + kt * 32;
        const __nv_bfloat16* pal = Al + (size_t)m0 * K + kt * 32;
        const __nv_bfloat16* pbh = Bh + (size_t)(kt * 32) * N + n0;
        const __nv_bfloat16* pbl = Bl + (size_t)(kt * 32) * N + n0;
        #pragma unroll
        for (int j = 0; j < 4; j++) CP_ASYNC16(b + aso[j],         pah + ago[j]);
        #pragma unroll
        for (int j = 0; j < 4; j++) CP_ASYNC16(b + ST_AL + aso[j], pal + ago[j]);
        #pragma unroll
        for (int j = 0; j < 4; j++) CP_ASYNC16(b + ST_BH + bso[j], pbh + bgo[j]);
        #pragma unroll
        for (int j = 0; j < 4; j++) CP_ASYNC16(b + ST_BL + bso[j], pbl + bgo[j]);
        CP_COMMIT();
    };

    load_stage(0, 0);

    for (int kt = 0; kt < KT; kt++) {
        if (kt + 1 < KT) {
            load_stage(kt + 1, (kt + 1) & 1);
            asm volatile("cp.async.wait_group 1;" ::: "memory");
        } else {
            asm volatile("cp.async.wait_group 0;" ::: "memory");
        }
        __syncthreads();

        const uint32_t b = sbase + (kt & 1) * ST_SZ;
        #pragma unroll
        for (int kh = 0; kh < 2; kh++) {
            // B fragments: 8 n-tiles x (hi, lo)
            uint32_t bh[8][2], bl[8][2];
            const int brow = kh * 16 + (lane & 15);
            #pragma unroll
            for (int ni = 0; ni < 8; ni++) {
                uint32_t col2 = (uint32_t)((wn * 64 + ni * 8) * 2);
                uint32_t ad = b + ST_BH + brow * 272 + col2;
                asm volatile("ldmatrix.sync.aligned.m8n8.x2.trans.shared.b16 {%0,%1},[%2];"
                             : "=r"(bh[ni][0]), "=r"(bh[ni][1]) : "r"(ad));
                ad = b + ST_BL + brow * 272 + col2;
                asm volatile("ldmatrix.sync.aligned.m8n8.x2.trans.shared.b16 {%0,%1},[%2];"
                             : "=r"(bl[ni][0]), "=r"(bl[ni][1]) : "r"(ad));
            }
            #pragma unroll
            for (int mi = 0; mi < 4; mi++) {
                const int arow = wm * 64 + mi * 16 + ((lane >> 3) & 1) * 8 + (lane & 7);
                const int acol = kh * 16 + (lane >> 4) * 8;
                uint32_t Ahf[4], Alf[4];
                uint32_t ad = b + arow * 80 + acol * 2;
                asm volatile("ldmatrix.sync.aligned.m8n8.x4.shared.b16 {%0,%1,%2,%3},[%4];"
                             : "=r"(Ahf[0]), "=r"(Ahf[1]), "=r"(Ahf[2]), "=r"(Ahf[3]) : "r"(ad));
                ad = b + ST_AL + arow * 80 + acol * 2;
                asm volatile("ldmatrix.sync.aligned.m8n8.x4.shared.b16 {%0,%1,%2,%3},[%4];"
                             : "=r"(Alf[0]), "=r"(Alf[1]), "=r"(Alf[2]), "=r"(Alf[3]) : "r"(ad));
                #pragma unroll
                for (int ni = 0; ni < 8; ni++) {
                    MMA_BF16(acc[mi][ni], Ahf, bh[ni]);
                    MMA_BF16(acc[mi][ni], Ahf, bl[ni]);
                    MMA_BF16(acc[mi][ni], Alf, bh[ni]);
                }
            }
        }
        __syncthreads();
    }

    // Epilogue
    const int rbase = m0 + wm * 64 + (lane >> 2);
    const int cbase = n0 + wn * 64 + (lane & 3) * 2;
    #pragma unroll
    for (int ni = 0; ni < 8; ni++) {
        int c = cbase + ni * 8;
        float b0 = 0.f, b1 = 0.f;
        if (bias) { b0 = bias[c]; b1 = bias[c + 1]; }
        #pragma unroll
        for (int mi = 0; mi < 4; mi++) {
            int r = rbase + mi * 16;
            *(float2*)(C + (size_t)r * N + c) =
                make_float2(acc[mi][ni][0] + b0, acc[mi][ni][1] + b1);
            *(float2*)(C + (size_t)(r + 8) * N + c) =
                make_float2(acc[mi][ni][2] + b0, acc[mi][ni][3] + b1);
        }
    }
}

// ---------------------------------------------------------------------------
// Per-(window, head) attention. Grid (1024, 12), 256 threads.
// ---------------------------------------------------------------------------
__global__ __launch_bounds__(256)
void attn_kernel(const float* __restrict__ qkv,
                 __nv_bfloat16* __restrict__ oh,
                 __nv_bfloat16* __restrict__ ol)
{
    __shared__ float sq[64][36];
    __shared__ float sk[64][36];
    __shared__ float sv[64][36];
    __shared__ float ss[64][68];

    const int wx   = blockIdx.x;
    const int head = blockIdx.y;
    const int b  = wx >> 6;
    const int wi = wx & 63;
    const int wh = wi >> 3;
    const int wc = wi & 7;
    const int tid = threadIdx.x;

    #pragma unroll
    for (int i = 0; i < 2; i++) {
        int f  = tid * 2 + i;
        int r  = f >> 3;
        int c4 = f & 7;
        int n = ((wh * 8 + (r >> 3)) << 6) + wc * 8 + (r & 7);
        const float* row = qkv + (size_t)(b * 4096 + n) * QKV_DIM + head * 32;
        *(float4*)&sq[r][c4 * 4] = *(const float4*)(row + c4 * 4);
        *(float4*)&sk[r][c4 * 4] = *(const float4*)(row + 384 + c4 * 4);
        *(float4*)&sv[r][c4 * 4] = *(const float4*)(row + 768 + c4 * 4);
    }
    __syncthreads();

    // QK^T, 4x4 register-blocked
    {
        const float scale = 0.17677669529663687f;
        int qr0 = (tid >> 4) * 4;
        int kr0 = (tid & 15) * 4;
        float a[4][4];
        #pragma unroll
        for (int i = 0; i < 4; i++)
            #pragma unroll
            for (int j = 0; j < 4; j++) a[i][j] = 0.0f;
        #pragma unroll
        for (int d = 0; d < 32; d += 4) {
            float4 qv[4], kv[4];
            #pragma unroll
            for (int i = 0; i < 4; i++) qv[i] = *(float4*)&sq[qr0 + i][d];
            #pragma unroll
            for (int j = 0; j < 4; j++) kv[j] = *(float4*)&sk[kr0 + j][d];
            #pragma unroll
            for (int i = 0; i < 4; i++)
                #pragma unroll
                for (int j = 0; j < 4; j++)
                    a[i][j] += qv[i].x * kv[j].x + qv[i].y * kv[j].y +
                               qv[i].z * kv[j].z + qv[i].w * kv[j].w;
        }
        #pragma unroll
        for (int i = 0; i < 4; i++)
            *(float4*)&ss[qr0 + i][kr0] = make_float4(
                a[i][0] * scale, a[i][1] * scale, a[i][2] * scale, a[i][3] * scale);
    }
    __syncthreads();

    // Softmax: 4 threads per row
    {
        int row  = tid >> 2;
        int part = (tid & 3) * 16;
        float m = -1e30f;
        #pragma unroll
        for (int j = 0; j < 16; j++) m = fmaxf(m, ss[row][part + j]);
        m = fmaxf(m, __shfl_xor_sync(0xffffffffu, m, 1));
        m = fmaxf(m, __shfl_xor_sync(0xffffffffu, m, 2));
        float sum = 0.0f;
        #pragma unroll
        for (int j = 0; j < 16; j++) {
            float e = __expf(ss[row][part + j] - m);
            ss[row][part + j] = e;
            sum += e;
        }
        sum += __shfl_xor_sync(0xffffffffu, sum, 1);
        sum += __shfl_xor_sync(0xffffffffu, sum, 2);
        float inv = 1.0f / sum;
        #pragma unroll
        for (int j = 0; j < 16; j++) ss[row][part + j] *= inv;
    }
    __syncthreads();

    // O = S @ V : 4 rows x 4 dims per thread, 128 threads.
    if (tid < 128) {
        int r0 = (tid >> 3) * 4;
        int d0 = (tid & 7) * 4;
        float4 o[4];
        #pragma unroll
        for (int i = 0; i < 4; i++) o[i] = make_float4(0.f, 0.f, 0.f, 0.f);
        #pragma unroll 4
        for (int k = 0; k < 64; k++) {
            float4 v = *(float4*)&sv[k][d0];
            #pragma unroll
            for (int i = 0; i < 4; i++) {
                float s = ss[r0 + i][k];
                o[i].x += s * v.x; o[i].y += s * v.y;
                o[i].z += s * v.z; o[i].w += s * v.w;
            }
        }
        #pragma unroll
        for (int i = 0; i < 4; i++) {
            int r = r0 + i;
            int n = ((wh * 8 + (r >> 3)) << 6) + wc * 8 + (r & 7);
            size_t base = (size_t)(b * 4096 + n) * C_DIM + head * 32 + d0;
            __nv_bfloat16 h0 = __float2bfloat16(o[i].x);
            __nv_bfloat16 h1 = __float2bfloat16(o[i].y);
            __nv_bfloat16 h2 = __float2bfloat16(o[i].z);
            __nv_bfloat16 h3 = __float2bfloat16(o[i].w);
            *(__nv_bfloat162*)(oh + base)     = __nv_bfloat162(h0, h1);
            *(__nv_bfloat162*)(oh + base + 2) = __nv_bfloat162(h2, h3);
            *(__nv_bfloat162*)(ol + base) = __nv_bfloat162(
                __float2bfloat16(o[i].x - __bfloat162float(h0)),
                __float2bfloat16(o[i].y - __bfloat162float(h1)));
            *(__nv_bfloat162*)(ol + base + 2) = __nv_bfloat162(
                __float2bfloat16(o[i].z - __bfloat162float(h2)),
                __float2bfloat16(o[i].w - __bfloat162float(h3)));
        }
    }
}

// ---------------------------------------------------------------------------
// Host launcher
// ---------------------------------------------------------------------------
extern "C" void kernel_launch(void* const* d_in, const int* in_sizes, int n_in,
                              void* d_out, int out_size)
{
    const float* x      = (const float*)d_in[0];
    const float* W_qkv  = (const float*)d_in[1];
    const float* b_qkv  = (const float*)d_in[2];
    const float* W_proj = (const float*)d_in[3];
    float* out = (float*)d_out;

    float *qkv;
    __nv_bfloat16 *xh, *xl, *ah, *al, *wqh, *wql, *wph, *wpl;
    cudaGetSymbolAddress((void**)&qkv, g_qkv);
    cudaGetSymbolAddress((void**)&xh,  g_xh);
    cudaGetSymbolAddress((void**)&xl,  g_xl);
    cudaGetSymbolAddress((void**)&ah,  g_ah);
    cudaGetSymbolAddress((void**)&al,  g_al);
    cudaGetSymbolAddress((void**)&wqh, g_wqh);
    cudaGetSymbolAddress((void**)&wql, g_wql);
    cudaGetSymbolAddress((void**)&wph, g_wph);
    cudaGetSymbolAddress((void**)&wpl, g_wpl);

    cudaFuncSetAttribute(gemm3_kernel,
                         cudaFuncAttributeMaxDynamicSharedMemorySize, GEMM_DYNSMEM);

    {
        int n4 = TOKENS * C_DIM / 4;
        split_kernel<<<(n4 + 255) / 256, 256>>>(x, xh, xl, n4);
        int w4 = C_DIM * QKV_DIM / 4;
        split_kernel<<<(w4 + 255) / 256, 256>>>(W_qkv, wqh, wql, w4);
        int p4 = C_DIM * C_DIM / 4;
        split_kernel<<<(p4 + 255) / 256, 256>>>(W_proj, wph, wpl, p4);
    }
    {
        dim3 grid(QKV_DIM / 128, TOKENS / 128);
        gemm3_kernel<<<grid, 128, GEMM_DYNSMEM>>>(xh, xl, wqh, wql, b_qkv, qkv,
                                                  QKV_DIM, C_DIM);
    }
    {
        dim3 grid(1024, 12);
        attn_kernel<<<grid, 256>>>(qkv, ah, al);
    }
    {
        dim3 grid(C_DIM / 128, TOKENS / 128);
        gemm3_kernel<<<grid, 128, GEMM_DYNSMEM>>>(ah, al, wph, wpl, nullptr, out,
                                                  C_DIM, C_DIM);
    }
}

// round 5
// speedup vs baseline: 3.7150x; 1.2755x over previous
#include <cuda_runtime.h>
#include <cuda_bf16.h>
#include <cstdint>

// x: [16,4096,384] fp32 -> out [16,4096,384] fp32
// 8x8 window attention over 64x64 grid, 12 heads, hd=32.

#define TOKENS   65536
#define C_DIM    384
#define QKV_DIM  1152

__device__ float          g_qkv[(size_t)TOKENS * QKV_DIM];
__device__ __nv_bfloat16  g_xh [(size_t)TOKENS * C_DIM];
__device__ __nv_bfloat16  g_xl [(size_t)TOKENS * C_DIM];
__device__ __nv_bfloat16  g_ah [(size_t)TOKENS * C_DIM];
__device__ __nv_bfloat16  g_al [(size_t)TOKENS * C_DIM];
__device__ __nv_bfloat16  g_wqh[(size_t)C_DIM * QKV_DIM];
__device__ __nv_bfloat16  g_wql[(size_t)C_DIM * QKV_DIM];
__device__ __nv_bfloat16  g_wph[(size_t)C_DIM * C_DIM];
__device__ __nv_bfloat16  g_wpl[(size_t)C_DIM * C_DIM];

static __device__ __forceinline__ uint32_t smem_u32(const void* p) {
    return (uint32_t)__cvta_generic_to_shared(p);
}

#define CP_ASYNC16(smem, gptr) \
    asm volatile("cp.async.cg.shared.global [%0], [%1], 16;" :: "r"(smem), "l"(gptr))
#define CP_COMMIT() asm volatile("cp.async.commit_group;" ::: "memory")

#define MMA_BF16(d, a, b)                                                      \
    asm volatile(                                                              \
        "mma.sync.aligned.m16n8k16.row.col.f32.bf16.bf16.f32 "                 \
        "{%0,%1,%2,%3},{%4,%5,%6,%7},{%8,%9},{%0,%1,%2,%3};"                   \
        : "+f"(d[0]), "+f"(d[1]), "+f"(d[2]), "+f"(d[3])                       \
        : "r"(a[0]), "r"(a[1]), "r"(a[2]), "r"(a[3]), "r"(b[0]), "r"(b[1]))

// ---------------------------------------------------------------------------
// fp32 -> (hi, lo) bf16 split
// ---------------------------------------------------------------------------
__global__ void split_kernel(const float* __restrict__ in,
                             __nv_bfloat16* __restrict__ hi,
                             __nv_bfloat16* __restrict__ lo, int n4)
{
    int i = blockIdx.x * blockDim.x + threadIdx.x;
    if (i >= n4) return;
    float4 v = ((const float4*)in)[i];
    __nv_bfloat16 h0 = __float2bfloat16(v.x), h1 = __float2bfloat16(v.y);
    __nv_bfloat16 h2 = __float2bfloat16(v.z), h3 = __float2bfloat16(v.w);
    __nv_bfloat162* hp = (__nv_bfloat162*)hi;
    __nv_bfloat162* lp = (__nv_bfloat162*)lo;
    hp[i*2]   = __nv_bfloat162(h0, h1);
    hp[i*2+1] = __nv_bfloat162(h2, h3);
    lp[i*2]   = __nv_bfloat162(__float2bfloat16(v.x - __bfloat162float(h0)),
                               __float2bfloat16(v.y - __bfloat162float(h1)));
    lp[i*2+1] = __nv_bfloat162(__float2bfloat16(v.z - __bfloat162float(h2)),
                               __float2bfloat16(v.w - __bfloat162float(h3)));
}

// ---------------------------------------------------------------------------
// 3x-bf16-split GEMM (mma.sync m16n8k16), cp.async double-buffered.
// CTA 128x128, 4 warps (2x2), warp tile 64x64, BK=32, 2 smem stages.
// ---------------------------------------------------------------------------
#define ST_AL 10240
#define ST_BH 20480
#define ST_BL 29184
#define ST_SZ 37888
#define GEMM_DYNSMEM (2 * ST_SZ)

__global__ __launch_bounds__(128, 2)
void gemm3_kernel(const __nv_bfloat16* __restrict__ Ah,
                  const __nv_bfloat16* __restrict__ Al,
                  const __nv_bfloat16* __restrict__ Bh,
                  const __nv_bfloat16* __restrict__ Bl,
                  const float* __restrict__ bias,
                  float* __restrict__ C, int N, int K)
{
    extern __shared__ char smem_raw[];
    const uint32_t sbase = smem_u32(smem_raw);

    const int tid  = threadIdx.x;
    const int lane = tid & 31;
    const int warp = tid >> 5;
    const int wm   = warp >> 1;
    const int wn   = warp & 1;
    const int m0   = blockIdx.y * 128;
    const int n0   = blockIdx.x * 128;
    const int KT   = K / 32;

    float acc[4][8][4];
    #pragma unroll
    for (int mi = 0; mi < 4; mi++)
        #pragma unroll
        for (int ni = 0; ni < 8; ni++)
            #pragma unroll
            for (int c = 0; c < 4; c++) acc[mi][ni][c] = 0.0f;

    uint32_t aso[4]; size_t ago[4];
    uint32_t bso[4]; size_t bgo[4];
    #pragma unroll
    for (int j = 0; j < 4; j++) {
        int idx = j * 128 + tid;
        int ar = idx >> 2, ac = idx & 3;
        aso[j] = (uint32_t)(ar * 80 + ac * 16);
        ago[j] = (size_t)ar * K + ac * 8;
        int br = idx >> 4, bc = idx & 15;
        bso[j] = (uint32_t)(br * 272 + bc * 16);
        bgo[j] = (size_t)br * N + bc * 8;
    }

    auto load_stage = [&](int kt, int st) {
        uint32_t b = sbase + st * ST_SZ;
        const __nv_bfloat16* pah = Ah + (size_t)m0 * K + kt * 32;
        const __nv_bfloat16* pal = Al + (size_t)m0 * K + kt * 32;
        const __nv_bfloat16* pbh = Bh + (size_t)(kt * 32) * N + n0;
        const __nv_bfloat16* pbl = Bl + (size_t)(kt * 32) * N + n0;
        #pragma unroll
        for (int j = 0; j < 4; j++) CP_ASYNC16(b + aso[j],         pah + ago[j]);
        #pragma unroll
        for (int j = 0; j < 4; j++) CP_ASYNC16(b + ST_AL + aso[j], pal + ago[j]);
        #pragma unroll
        for (int j = 0; j < 4; j++) CP_ASYNC16(b + ST_BH + bso[j], pbh + bgo[j]);
        #pragma unroll
        for (int j = 0; j < 4; j++) CP_ASYNC16(b + ST_BL + bso[j], pbl + bgo[j]);
        CP_COMMIT();
    };

    load_stage(0, 0);

    for (int kt = 0; kt < KT; kt++) {
        if (kt + 1 < KT) {
            load_stage(kt + 1, (kt + 1) & 1);
            asm volatile("cp.async.wait_group 1;" ::: "memory");
        } else {
            asm volatile("cp.async.wait_group 0;" ::: "memory");
        }
        __syncthreads();

        const uint32_t b = sbase + (kt & 1) * ST_SZ;
        #pragma unroll
        for (int kh = 0; kh < 2; kh++) {
            uint32_t bh[8][2], bl[8][2];
            const int brow = kh * 16 + (lane & 15);
            #pragma unroll
            for (int ni = 0; ni < 8; ni++) {
                uint32_t col2 = (uint32_t)((wn * 64 + ni * 8) * 2);
                uint32_t ad = b + ST_BH + brow * 272 + col2;
                asm volatile("ldmatrix.sync.aligned.m8n8.x2.trans.shared.b16 {%0,%1},[%2];"
                             : "=r"(bh[ni][0]), "=r"(bh[ni][1]) : "r"(ad));
                ad = b + ST_BL + brow * 272 + col2;
                asm volatile("ldmatrix.sync.aligned.m8n8.x2.trans.shared.b16 {%0,%1},[%2];"
                             : "=r"(bl[ni][0]), "=r"(bl[ni][1]) : "r"(ad));
            }
            #pragma unroll
            for (int mi = 0; mi < 4; mi++) {
                const int arow = wm * 64 + mi * 16 + ((lane >> 3) & 1) * 8 + (lane & 7);
                const int acol = kh * 16 + (lane >> 4) * 8;
                uint32_t Ahf[4], Alf[4];
                uint32_t ad = b + arow * 80 + acol * 2;
                asm volatile("ldmatrix.sync.aligned.m8n8.x4.shared.b16 {%0,%1,%2,%3},[%4];"
                             : "=r"(Ahf[0]), "=r"(Ahf[1]), "=r"(Ahf[2]), "=r"(Ahf[3]) : "r"(ad));
                ad = b + ST_AL + arow * 80 + acol * 2;
                asm volatile("ldmatrix.sync.aligned.m8n8.x4.shared.b16 {%0,%1,%2,%3},[%4];"
                             : "=r"(Alf[0]), "=r"(Alf[1]), "=r"(Alf[2]), "=r"(Alf[3]) : "r"(ad));
                #pragma unroll
                for (int ni = 0; ni < 8; ni++) {
                    MMA_BF16(acc[mi][ni], Ahf, bh[ni]);
                    MMA_BF16(acc[mi][ni], Ahf, bl[ni]);
                    MMA_BF16(acc[mi][ni], Alf, bh[ni]);
                }
            }
        }
        __syncthreads();
    }

    const int rbase = m0 + wm * 64 + (lane >> 2);
    const int cbase = n0 + wn * 64 + (lane & 3) * 2;
    #pragma unroll
    for (int ni = 0; ni < 8; ni++) {
        int c = cbase + ni * 8;
        float b0 = 0.f, b1 = 0.f;
        if (bias) { b0 = bias[c]; b1 = bias[c + 1]; }
        #pragma unroll
        for (int mi = 0; mi < 4; mi++) {
            int r = rbase + mi * 16;
            *(float2*)(C + (size_t)r * N + c) =
                make_float2(acc[mi][ni][0] + b0, acc[mi][ni][1] + b1);
            *(float2*)(C + (size_t)(r + 8) * N + c) =
                make_float2(acc[mi][ni][2] + b0, acc[mi][ni][3] + b1);
        }
    }
}

// ---------------------------------------------------------------------------
// Tensor-core window attention. One block per (window, head): 128 threads,
// 4 warps; warp w owns S rows 16w..16w+15.
//   S = Q@K^T   (3x bf16 split, fp32 C-fragments, no smem for S)
//   softmax     (register-resident, shfl_xor over 4-lane row groups)
//   O = P@V     (P fragments built in-register from S fragments; 3x split)
// Emits hi/lo bf16 split of O directly.
// ---------------------------------------------------------------------------
__global__ __launch_bounds__(128)
void attn_tc_kernel(const float* __restrict__ qkv,
                    __nv_bfloat16* __restrict__ oh,
                    __nv_bfloat16* __restrict__ ol)
{
    __shared__ __nv_bfloat16 sQh[64][40], sQl[64][40];
    __shared__ __nv_bfloat16 sKh[64][40], sKl[64][40];
    __shared__ __nv_bfloat16 sVh[64][40], sVl[64][40];

    const int wx   = blockIdx.x;
    const int head = blockIdx.y;
    const int b  = wx >> 6;
    const int wi = wx & 63;
    const int wh = wi >> 3;
    const int wc = wi & 7;
    const int tid  = threadIdx.x;
    const int lane = tid & 31;
    const int warp = tid >> 5;

    // ---- load + split-convert q,k,v into smem (4 float4 per matrix/thread)
    #pragma unroll
    for (int i = 0; i < 4; i++) {
        int f  = i * 128 + tid;          // 0..511
        int r  = f >> 3;                 // token slot 0..63
        int c4 = f & 7;                  // float4 within 32
        int n = ((wh * 8 + (r >> 3)) << 6) + wc * 8 + (r & 7);
        const float* row = qkv + (size_t)(b * 4096 + n) * QKV_DIM + head * 32;
        float4 qv = *(const float4*)(row + c4 * 4);
        float4 kv = *(const float4*)(row + 384 + c4 * 4);
        float4 vv = *(const float4*)(row + 768 + c4 * 4);
        #pragma unroll
        for (int m = 0; m < 3; m++) {
            float4 v = (m == 0) ? qv : (m == 1) ? kv : vv;
            __nv_bfloat162 H0 = __floats2bfloat162_rn(v.x, v.y);
            __nv_bfloat162 H1 = __floats2bfloat162_rn(v.z, v.w);
            __nv_bfloat162 L0 = __floats2bfloat162_rn(v.x - __bfloat162float(H0.x),
                                                      v.y - __bfloat162float(H0.y));
            __nv_bfloat162 L1 = __floats2bfloat162_rn(v.z - __bfloat162float(H1.x),
                                                      v.w - __bfloat162float(H1.y));
            __nv_bfloat16* ph = (m == 0) ? &sQh[r][c4*4] : (m == 1) ? &sKh[r][c4*4] : &sVh[r][c4*4];
            __nv_bfloat16* pl = (m == 0) ? &sQl[r][c4*4] : (m == 1) ? &sKl[r][c4*4] : &sVl[r][c4*4];
            *(__nv_bfloat162*)(ph)     = H0;
            *(__nv_bfloat162*)(ph + 2) = H1;
            *(__nv_bfloat162*)(pl)     = L0;
            *(__nv_bfloat162*)(pl + 2) = L1;
        }
    }
    __syncthreads();

    // ---- S = Q @ K^T : warp stripe rows 16*warp..+15; cS[nt] = n-tile nt.
    float cS[8][4];
    #pragma unroll
    for (int nt = 0; nt < 8; nt++)
        #pragma unroll
        for (int c = 0; c < 4; c++) cS[nt][c] = 0.0f;

    #pragma unroll
    for (int kt = 0; kt < 2; kt++) {
        // Q A-fragments (x4 non-trans)
        const int arow = warp * 16 + ((lane >> 3) & 1) * 8 + (lane & 7);
        const int acol = kt * 16 + (lane >> 4) * 8;
        uint32_t qh[4], ql[4];
        uint32_t ad = smem_u32(&sQh[arow][acol]);
        asm volatile("ldmatrix.sync.aligned.m8n8.x4.shared.b16 {%0,%1,%2,%3},[%4];"
                     : "=r"(qh[0]), "=r"(qh[1]), "=r"(qh[2]), "=r"(qh[3]) : "r"(ad));
        ad = smem_u32(&sQl[arow][acol]);
        asm volatile("ldmatrix.sync.aligned.m8n8.x4.shared.b16 {%0,%1,%2,%3},[%4];"
                     : "=r"(ql[0]), "=r"(ql[1]), "=r"(ql[2]), "=r"(ql[3]) : "r"(ad));
        #pragma unroll
        for (int nt = 0; nt < 8; nt++) {
            // K B-fragments (x2 NON-trans: K is [token][d] = n-major rows of k)
            const int brow = nt * 8 + (lane & 7);
            const int bcol = kt * 16 + ((lane >> 3) & 1) * 8;
            uint32_t kh2[2], kl2[2];
            uint32_t bd = smem_u32(&sKh[brow][bcol]);
            asm volatile("ldmatrix.sync.aligned.m8n8.x2.shared.b16 {%0,%1},[%2];"
                         : "=r"(kh2[0]), "=r"(kh2[1]) : "r"(bd));
            bd = smem_u32(&sKl[brow][bcol]);
            asm volatile("ldmatrix.sync.aligned.m8n8.x2.shared.b16 {%0,%1},[%2];"
                         : "=r"(kl2[0]), "=r"(kl2[1]) : "r"(bd));
            MMA_BF16(cS[nt], qh, kh2);
            MMA_BF16(cS[nt], ql, kh2);
            MMA_BF16(cS[nt], qh, kl2);
        }
    }

    // ---- register softmax over rows r0 = 16*warp + (lane>>2) and r0+8.
    const float scale = 0.17677669529663687f;   // 1/sqrt(32)
    {
        float m0 = -1e30f, m1 = -1e30f;
        #pragma unroll
        for (int nt = 0; nt < 8; nt++) {
            m0 = fmaxf(m0, fmaxf(cS[nt][0], cS[nt][1]));
            m1 = fmaxf(m1, fmaxf(cS[nt][2], cS[nt][3]));
        }
        m0 = fmaxf(m0, __shfl_xor_sync(0xffffffffu, m0, 1));
        m0 = fmaxf(m0, __shfl_xor_sync(0xffffffffu, m0, 2));
        m1 = fmaxf(m1, __shfl_xor_sync(0xffffffffu, m1, 1));
        m1 = fmaxf(m1, __shfl_xor_sync(0xffffffffu, m1, 2));
        float s0 = 0.f, s1 = 0.f;
        #pragma unroll
        for (int nt = 0; nt < 8; nt++) {
            cS[nt][0] = __expf((cS[nt][0] - m0) * scale); s0 += cS[nt][0];
            cS[nt][1] = __expf((cS[nt][1] - m0) * scale); s0 += cS[nt][1];
            cS[nt][2] = __expf((cS[nt][2] - m1) * scale); s1 += cS[nt][2];
            cS[nt][3] = __expf((cS[nt][3] - m1) * scale); s1 += cS[nt][3];
        }
        s0 += __shfl_xor_sync(0xffffffffu, s0, 1);
        s0 += __shfl_xor_sync(0xffffffffu, s0, 2);
        s1 += __shfl_xor_sync(0xffffffffu, s1, 1);
        s1 += __shfl_xor_sync(0xffffffffu, s1, 2);
        float i0 = 1.0f / s0, i1 = 1.0f / s1;
        #pragma unroll
        for (int nt = 0; nt < 8; nt++) {
            cS[nt][0] *= i0; cS[nt][1] *= i0;
            cS[nt][2] *= i1; cS[nt][3] *= i1;
        }
    }

    // ---- build P A-fragments in-register (S C-frag layout == P A-frag layout)
    uint32_t ph[4][4], pl[4][4];
    #pragma unroll
    for (int kt = 0; kt < 4; kt++) {
        #pragma unroll
        for (int half = 0; half < 2; half++) {       // half 0: ntile 2kt, 1: 2kt+1
            int nt = 2 * kt + half;
            __nv_bfloat162 H0 = __floats2bfloat162_rn(cS[nt][0], cS[nt][1]);
            __nv_bfloat162 H1 = __floats2bfloat162_rn(cS[nt][2], cS[nt][3]);
            __nv_bfloat162 L0 = __floats2bfloat162_rn(cS[nt][0] - __bfloat162float(H0.x),
                                                      cS[nt][1] - __bfloat162float(H0.y));
            __nv_bfloat162 L1 = __floats2bfloat162_rn(cS[nt][2] - __bfloat162float(H1.x),
                                                      cS[nt][3] - __bfloat162float(H1.y));
            ph[kt][half * 2 + 0] = *(uint32_t*)&H0;   // a0/a2: row g0
            ph[kt][half * 2 + 1] = *(uint32_t*)&H1;   // a1/a3: row g0+8
            pl[kt][half * 2 + 0] = *(uint32_t*)&L0;
            pl[kt][half * 2 + 1] = *(uint32_t*)&L1;
        }
    }

    // ---- O = P @ V : n = 32 dims (4 n-tiles), k = 64 (4 k-tiles)
    float cO[4][4];
    #pragma unroll
    for (int nt = 0; nt < 4; nt++)
        #pragma unroll
        for (int c = 0; c < 4; c++) cO[nt][c] = 0.0f;

    #pragma unroll
    for (int kt = 0; kt < 4; kt++) {
        const int vrow = kt * 16 + (lane & 15);
        #pragma unroll
        for (int nt = 0; nt < 4; nt++) {
            uint32_t vh2[2], vl2[2];
            uint32_t ad = smem_u32(&sVh[vrow][nt * 8]);
            asm volatile("ldmatrix.sync.aligned.m8n8.x2.trans.shared.b16 {%0,%1},[%2];"
                         : "=r"(vh2[0]), "=r"(vh2[1]) : "r"(ad));
            ad = smem_u32(&sVl[vrow][nt * 8]);
            asm volatile("ldmatrix.sync.aligned.m8n8.x2.trans.shared.b16 {%0,%1},[%2];"
                         : "=r"(vl2[0]), "=r"(vl2[1]) : "r"(ad));
            MMA_BF16(cO[nt], ph[kt], vh2);
            MMA_BF16(cO[nt], pl[kt], vh2);
            MMA_BF16(cO[nt], ph[kt], vl2);
        }
    }

    // ---- write O as hi/lo bf16 split (rows r0 and r0+8, cols 8nt+2c)
    {
        const int g0 = lane >> 2;
        const int c2 = (lane & 3) * 2;
        #pragma unroll
        for (int half = 0; half < 2; half++) {
            int r = warp * 16 + g0 + half * 8;
            int n = ((wh * 8 + (r >> 3)) << 6) + wc * 8 + (r & 7);
            size_t base = (size_t)(b * 4096 + n) * C_DIM + head * 32;
            #pragma unroll
            for (int nt = 0; nt < 4; nt++) {
                float v0 = cO[nt][half * 2 + 0];
                float v1 = cO[nt][half * 2 + 1];
                __nv_bfloat162 H = __floats2bfloat162_rn(v0, v1);
                __nv_bfloat162 L = __floats2bfloat162_rn(v0 - __bfloat162float(H.x),
                                                         v1 - __bfloat162float(H.y));
                size_t off = base + nt * 8 + c2;
                *(__nv_bfloat162*)(oh + off) = H;
                *(__nv_bfloat162*)(ol + off) = L;
            }
        }
    }
}

// ---------------------------------------------------------------------------
// Host launcher
// ---------------------------------------------------------------------------
extern "C" void kernel_launch(void* const* d_in, const int* in_sizes, int n_in,
                              void* d_out, int out_size)
{
    const float* x      = (const float*)d_in[0];
    const float* W_qkv  = (const float*)d_in[1];
    const float* b_qkv  = (const float*)d_in[2];
    const float* W_proj = (const float*)d_in[3];
    float* out = (float*)d_out;

    float *qkv;
    __nv_bfloat16 *xh, *xl, *ah, *al, *wqh, *wql, *wph, *wpl;
    cudaGetSymbolAddress((void**)&qkv, g_qkv);
    cudaGetSymbolAddress((void**)&xh,  g_xh);
    cudaGetSymbolAddress((void**)&xl,  g_xl);
    cudaGetSymbolAddress((void**)&ah,  g_ah);
    cudaGetSymbolAddress((void**)&al,  g_al);
    cudaGetSymbolAddress((void**)&wqh, g_wqh);
    cudaGetSymbolAddress((void**)&wql, g_wql);
    cudaGetSymbolAddress((void**)&wph, g_wph);
    cudaGetSymbolAddress((void**)&wpl, g_wpl);

    cudaFuncSetAttribute(gemm3_kernel,
                         cudaFuncAttributeMaxDynamicSharedMemorySize, GEMM_DYNSMEM);

    {
        int n4 = TOKENS * C_DIM / 4;
        split_kernel<<<(n4 + 255) / 256, 256>>>(x, xh, xl, n4);
        int w4 = C_DIM * QKV_DIM / 4;
        split_kernel<<<(w4 + 255) / 256, 256>>>(W_qkv, wqh, wql, w4);
        int p4 = C_DIM * C_DIM / 4;
        split_kernel<<<(p4 + 255) / 256, 256>>>(W_proj, wph, wpl, p4);
    }
    {
        dim3 grid(QKV_DIM / 128, TOKENS / 128);
        gemm3_kernel<<<grid, 128, GEMM_DYNSMEM>>>(xh, xl, wqh, wql, b_qkv, qkv,
                                                  QKV_DIM, C_DIM);
    }
    {
        dim3 grid(1024, 12);
        attn_tc_kernel<<<grid, 128>>>(qkv, ah, al);
    }
    {
        dim3 grid(C_DIM / 128, TOKENS / 128);
        gemm3_kernel<<<grid, 128, GEMM_DYNSMEM>>>(ah, al, wph, wpl, nullptr, out,
                                                  C_DIM, C_DIM);
    }
}

// round 6
// speedup vs baseline: 3.7336x; 1.0050x over previous
#include <cuda_runtime.h>
#include <cuda_bf16.h>
#include <cstdint>

// x: [16,4096,384] fp32 -> out [16,4096,384] fp32
// 8x8 window attention over 64x64 grid, 12 heads, hd=32.

#define TOKENS   65536
#define C_DIM    384
#define QKV_DIM  1152

__device__ float          g_qkv[(size_t)TOKENS * QKV_DIM];
__device__ __nv_bfloat16  g_xh [(size_t)TOKENS * C_DIM];
__device__ __nv_bfloat16  g_xl [(size_t)TOKENS * C_DIM];
__device__ __nv_bfloat16  g_ah [(size_t)TOKENS * C_DIM];
__device__ __nv_bfloat16  g_al [(size_t)TOKENS * C_DIM];
__device__ __nv_bfloat16  g_wqh[(size_t)C_DIM * QKV_DIM];
__device__ __nv_bfloat16  g_wql[(size_t)C_DIM * QKV_DIM];
__device__ __nv_bfloat16  g_wph[(size_t)C_DIM * C_DIM];
__device__ __nv_bfloat16  g_wpl[(size_t)C_DIM * C_DIM];

static __device__ __forceinline__ uint32_t smem_u32(const void* p) {
    return (uint32_t)__cvta_generic_to_shared(p);
}

#define CP_ASYNC16(smem, gptr) \
    asm volatile("cp.async.cg.shared.global [%0], [%1], 16;" :: "r"(smem), "l"(gptr))
#define CP_COMMIT() asm volatile("cp.async.commit_group;" ::: "memory")

#define MMA_BF16(d, a, b)                                                      \
    asm volatile(                                                              \
        "mma.sync.aligned.m16n8k16.row.col.f32.bf16.bf16.f32 "                 \
        "{%0,%1,%2,%3},{%4,%5,%6,%7},{%8,%9},{%0,%1,%2,%3};"                   \
        : "+f"(d[0]), "+f"(d[1]), "+f"(d[2]), "+f"(d[3])                       \
        : "r"(a[0]), "r"(a[1]), "r"(a[2]), "r"(a[3]), "r"(b[0]), "r"(b[1]))

// ---------------------------------------------------------------------------
// fp32 -> (hi, lo) bf16 split
// ---------------------------------------------------------------------------
__global__ void split_kernel(const float* __restrict__ in,
                             __nv_bfloat16* __restrict__ hi,
                             __nv_bfloat16* __restrict__ lo, int n4)
{
    int i = blockIdx.x * blockDim.x + threadIdx.x;
    if (i >= n4) return;
    float4 v = ((const float4*)in)[i];
    __nv_bfloat16 h0 = __float2bfloat16(v.x), h1 = __float2bfloat16(v.y);
    __nv_bfloat16 h2 = __float2bfloat16(v.z), h3 = __float2bfloat16(v.w);
    __nv_bfloat162* hp = (__nv_bfloat162*)hi;
    __nv_bfloat162* lp = (__nv_bfloat162*)lo;
    hp[i*2]   = __nv_bfloat162(h0, h1);
    hp[i*2+1] = __nv_bfloat162(h2, h3);
    lp[i*2]   = __nv_bfloat162(__float2bfloat16(v.x - __bfloat162float(h0)),
                               __float2bfloat16(v.y - __bfloat162float(h1)));
    lp[i*2+1] = __nv_bfloat162(__float2bfloat16(v.z - __bfloat162float(h2)),
                               __float2bfloat16(v.w - __bfloat162float(h3)));
}

// ---------------------------------------------------------------------------
// 3x-bf16-split GEMM (mma.sync m16n8k16), cp.async 3-stage pipeline,
// ONE __syncthreads per k-tile.
// CTA 128x128, 4 warps (2x2), warp tile 64x64, BK=32.
// ---------------------------------------------------------------------------
#define ST_AL 10240
#define ST_BH 20480
#define ST_BL 29184
#define ST_SZ 37888
#define N_STAGES 3
#define GEMM_DYNSMEM (N_STAGES * ST_SZ)

__global__ __launch_bounds__(128, 2)
void gemm3_kernel(const __nv_bfloat16* __restrict__ Ah,
                  const __nv_bfloat16* __restrict__ Al,
                  const __nv_bfloat16* __restrict__ Bh,
                  const __nv_bfloat16* __restrict__ Bl,
                  const float* __restrict__ bias,
                  float* __restrict__ C, int N, int K)
{
    extern __shared__ char smem_raw[];
    const uint32_t sbase = smem_u32(smem_raw);

    const int tid  = threadIdx.x;
    const int lane = tid & 31;
    const int warp = tid >> 5;
    const int wm   = warp >> 1;
    const int wn   = warp & 1;
    const int m0   = blockIdx.y * 128;
    const int n0   = blockIdx.x * 128;
    const int KT   = K / 32;

    float acc[4][8][4];
    #pragma unroll
    for (int mi = 0; mi < 4; mi++)
        #pragma unroll
        for (int ni = 0; ni < 8; ni++)
            #pragma unroll
            for (int c = 0; c < 4; c++) acc[mi][ni][c] = 0.0f;

    uint32_t aso[4]; size_t ago[4];
    uint32_t bso[4]; size_t bgo[4];
    #pragma unroll
    for (int j = 0; j < 4; j++) {
        int idx = j * 128 + tid;
        int ar = idx >> 2, ac = idx & 3;
        aso[j] = (uint32_t)(ar * 80 + ac * 16);
        ago[j] = (size_t)ar * K + ac * 8;
        int br = idx >> 4, bc = idx & 15;
        bso[j] = (uint32_t)(br * 272 + bc * 16);
        bgo[j] = (size_t)br * N + bc * 8;
    }

    auto load_stage = [&](int kt, int st) {
        uint32_t b = sbase + st * ST_SZ;
        const __nv_bfloat16* pah = Ah + (size_t)m0 * K + kt * 32;
        const __nv_bfloat16* pal = Al + (size_t)m0 * K + kt * 32;
        const __nv_bfloat16* pbh = Bh + (size_t)(kt * 32) * N + n0;
        const __nv_bfloat16* pbl = Bl + (size_t)(kt * 32) * N + n0;
        #pragma unroll
        for (int j = 0; j < 4; j++) CP_ASYNC16(b + aso[j],         pah + ago[j]);
        #pragma unroll
        for (int j = 0; j < 4; j++) CP_ASYNC16(b + ST_AL + aso[j], pal + ago[j]);
        #pragma unroll
        for (int j = 0; j < 4; j++) CP_ASYNC16(b + ST_BH + bso[j], pbh + bgo[j]);
        #pragma unroll
        for (int j = 0; j < 4; j++) CP_ASYNC16(b + ST_BL + bso[j], pbl + bgo[j]);
        CP_COMMIT();
    };

    // Prologue: stages 0 and 1 in flight.
    load_stage(0, 0);
    load_stage(1, 1);

    int stage = 0;
    for (int kt = 0; kt < KT; kt++) {
        // Stage kt must be complete. Committed groups so far cover stages
        // 0..min(kt+1, KT-1); allow 1 pending unless we're at the tail.
        if (kt + 1 < KT) {
            asm volatile("cp.async.wait_group 1;" ::: "memory");
        } else {
            asm volatile("cp.async.wait_group 0;" ::: "memory");
        }
        __syncthreads();

        // Buffer (kt+2)%3 == (kt-1)%3 is free now — refill it while computing.
        if (kt + 2 < KT) {
            int st2 = stage + 2; if (st2 >= N_STAGES) st2 -= N_STAGES;
            load_stage(kt + 2, st2);
        }

        const uint32_t b = sbase + stage * ST_SZ;
        #pragma unroll
        for (int kh = 0; kh < 2; kh++) {
            uint32_t bh[8][2], bl[8][2];
            const int brow = kh * 16 + (lane & 15);
            #pragma unroll
            for (int ni = 0; ni < 8; ni++) {
                uint32_t col2 = (uint32_t)((wn * 64 + ni * 8) * 2);
                uint32_t ad = b + ST_BH + brow * 272 + col2;
                asm volatile("ldmatrix.sync.aligned.m8n8.x2.trans.shared.b16 {%0,%1},[%2];"
                             : "=r"(bh[ni][0]), "=r"(bh[ni][1]) : "r"(ad));
                ad = b + ST_BL + brow * 272 + col2;
                asm volatile("ldmatrix.sync.aligned.m8n8.x2.trans.shared.b16 {%0,%1},[%2];"
                             : "=r"(bl[ni][0]), "=r"(bl[ni][1]) : "r"(ad));
            }
            #pragma unroll
            for (int mi = 0; mi < 4; mi++) {
                const int arow = wm * 64 + mi * 16 + ((lane >> 3) & 1) * 8 + (lane & 7);
                const int acol = kh * 16 + (lane >> 4) * 8;
                uint32_t Ahf[4], Alf[4];
                uint32_t ad = b + arow * 80 + acol * 2;
                asm volatile("ldmatrix.sync.aligned.m8n8.x4.shared.b16 {%0,%1,%2,%3},[%4];"
                             : "=r"(Ahf[0]), "=r"(Ahf[1]), "=r"(Ahf[2]), "=r"(Ahf[3]) : "r"(ad));
                ad = b + ST_AL + arow * 80 + acol * 2;
                asm volatile("ldmatrix.sync.aligned.m8n8.x4.shared.b16 {%0,%1,%2,%3},[%4];"
                             : "=r"(Alf[0]), "=r"(Alf[1]), "=r"(Alf[2]), "=r"(Alf[3]) : "r"(ad));
                #pragma unroll
                for (int ni = 0; ni < 8; ni++) {
                    MMA_BF16(acc[mi][ni], Ahf, bh[ni]);
                    MMA_BF16(acc[mi][ni], Ahf, bl[ni]);
                    MMA_BF16(acc[mi][ni], Alf, bh[ni]);
                }
            }
        }
        stage++; if (stage >= N_STAGES) stage = 0;
    }

    const int rbase = m0 + wm * 64 + (lane >> 2);
    const int cbase = n0 + wn * 64 + (lane & 3) * 2;
    #pragma unroll
    for (int ni = 0; ni < 8; ni++) {
        int c = cbase + ni * 8;
        float b0 = 0.f, b1 = 0.f;
        if (bias) { b0 = bias[c]; b1 = bias[c + 1]; }
        #pragma unroll
        for (int mi = 0; mi < 4; mi++) {
            int r = rbase + mi * 16;
            *(float2*)(C + (size_t)r * N + c) =
                make_float2(acc[mi][ni][0] + b0, acc[mi][ni][1] + b1);
            *(float2*)(C + (size_t)(r + 8) * N + c) =
                make_float2(acc[mi][ni][2] + b0, acc[mi][ni][3] + b1);
        }
    }
}

// ---------------------------------------------------------------------------
// Tensor-core window attention (unchanged from round 5).
// ---------------------------------------------------------------------------
__global__ __launch_bounds__(128)
void attn_tc_kernel(const float* __restrict__ qkv,
                    __nv_bfloat16* __restrict__ oh,
                    __nv_bfloat16* __restrict__ ol)
{
    __shared__ __nv_bfloat16 sQh[64][40], sQl[64][40];
    __shared__ __nv_bfloat16 sKh[64][40], sKl[64][40];
    __shared__ __nv_bfloat16 sVh[64][40], sVl[64][40];

    const int wx   = blockIdx.x;
    const int head = blockIdx.y;
    const int b  = wx >> 6;
    const int wi = wx & 63;
    const int wh = wi >> 3;
    const int wc = wi & 7;
    const int tid  = threadIdx.x;
    const int lane = tid & 31;
    const int warp = tid >> 5;

    #pragma unroll
    for (int i = 0; i < 4; i++) {
        int f  = i * 128 + tid;
        int r  = f >> 3;
        int c4 = f & 7;
        int n = ((wh * 8 + (r >> 3)) << 6) + wc * 8 + (r & 7);
        const float* row = qkv + (size_t)(b * 4096 + n) * QKV_DIM + head * 32;
        float4 qv = *(const float4*)(row + c4 * 4);
        float4 kv = *(const float4*)(row + 384 + c4 * 4);
        float4 vv = *(const float4*)(row + 768 + c4 * 4);
        #pragma unroll
        for (int m = 0; m < 3; m++) {
            float4 v = (m == 0) ? qv : (m == 1) ? kv : vv;
            __nv_bfloat162 H0 = __floats2bfloat162_rn(v.x, v.y);
            __nv_bfloat162 H1 = __floats2bfloat162_rn(v.z, v.w);
            __nv_bfloat162 L0 = __floats2bfloat162_rn(v.x - __bfloat162float(H0.x),
                                                      v.y - __bfloat162float(H0.y));
            __nv_bfloat162 L1 = __floats2bfloat162_rn(v.z - __bfloat162float(H1.x),
                                                      v.w - __bfloat162float(H1.y));
            __nv_bfloat16* ph = (m == 0) ? &sQh[r][c4*4] : (m == 1) ? &sKh[r][c4*4] : &sVh[r][c4*4];
            __nv_bfloat16* pl = (m == 0) ? &sQl[r][c4*4] : (m == 1) ? &sKl[r][c4*4] : &sVl[r][c4*4];
            *(__nv_bfloat162*)(ph)     = H0;
            *(__nv_bfloat162*)(ph + 2) = H1;
            *(__nv_bfloat162*)(pl)     = L0;
            *(__nv_bfloat162*)(pl + 2) = L1;
        }
    }
    __syncthreads();

    float cS[8][4];
    #pragma unroll
    for (int nt = 0; nt < 8; nt++)
        #pragma unroll
        for (int c = 0; c < 4; c++) cS[nt][c] = 0.0f;

    #pragma unroll
    for (int kt = 0; kt < 2; kt++) {
        const int arow = warp * 16 + ((lane >> 3) & 1) * 8 + (lane & 7);
        const int acol = kt * 16 + (lane >> 4) * 8;
        uint32_t qh[4], ql[4];
        uint32_t ad = smem_u32(&sQh[arow][acol]);
        asm volatile("ldmatrix.sync.aligned.m8n8.x4.shared.b16 {%0,%1,%2,%3},[%4];"
                     : "=r"(qh[0]), "=r"(qh[1]), "=r"(qh[2]), "=r"(qh[3]) : "r"(ad));
        ad = smem_u32(&sQl[arow][acol]);
        asm volatile("ldmatrix.sync.aligned.m8n8.x4.shared.b16 {%0,%1,%2,%3},[%4];"
                     : "=r"(ql[0]), "=r"(ql[1]), "=r"(ql[2]), "=r"(ql[3]) : "r"(ad));
        #pragma unroll
        for (int nt = 0; nt < 8; nt++) {
            const int brow = nt * 8 + (lane & 7);
            const int bcol = kt * 16 + ((lane >> 3) & 1) * 8;
            uint32_t kh2[2], kl2[2];
            uint32_t bd = smem_u32(&sKh[brow][bcol]);
            asm volatile("ldmatrix.sync.aligned.m8n8.x2.shared.b16 {%0,%1},[%2];"
                         : "=r"(kh2[0]), "=r"(kh2[1]) : "r"(bd));
            bd = smem_u32(&sKl[brow][bcol]);
            asm volatile("ldmatrix.sync.aligned.m8n8.x2.shared.b16 {%0,%1},[%2];"
                         : "=r"(kl2[0]), "=r"(kl2[1]) : "r"(bd));
            MMA_BF16(cS[nt], qh, kh2);
            MMA_BF16(cS[nt], ql, kh2);
            MMA_BF16(cS[nt], qh, kl2);
        }
    }

    const float scale = 0.17677669529663687f;
    {
        float m0 = -1e30f, m1 = -1e30f;
        #pragma unroll
        for (int nt = 0; nt < 8; nt++) {
            m0 = fmaxf(m0, fmaxf(cS[nt][0], cS[nt][1]));
            m1 = fmaxf(m1, fmaxf(cS[nt][2], cS[nt][3]));
        }
        m0 = fmaxf(m0, __shfl_xor_sync(0xffffffffu, m0, 1));
        m0 = fmaxf(m0, __shfl_xor_sync(0xffffffffu, m0, 2));
        m1 = fmaxf(m1, __shfl_xor_sync(0xffffffffu, m1, 1));
        m1 = fmaxf(m1, __shfl_xor_sync(0xffffffffu, m1, 2));
        float s0 = 0.f, s1 = 0.f;
        #pragma unroll
        for (int nt = 0; nt < 8; nt++) {
            cS[nt][0] = __expf((cS[nt][0] - m0) * scale); s0 += cS[nt][0];
            cS[nt][1] = __expf((cS[nt][1] - m0) * scale); s0 += cS[nt][1];
            cS[nt][2] = __expf((cS[nt][2] - m1) * scale); s1 += cS[nt][2];
            cS[nt][3] = __expf((cS[nt][3] - m1) * scale); s1 += cS[nt][3];
        }
        s0 += __shfl_xor_sync(0xffffffffu, s0, 1);
        s0 += __shfl_xor_sync(0xffffffffu, s0, 2);
        s1 += __shfl_xor_sync(0xffffffffu, s1, 1);
        s1 += __shfl_xor_sync(0xffffffffu, s1, 2);
        float i0 = 1.0f / s0, i1 = 1.0f / s1;
        #pragma unroll
        for (int nt = 0; nt < 8; nt++) {
            cS[nt][0] *= i0; cS[nt][1] *= i0;
            cS[nt][2] *= i1; cS[nt][3] *= i1;
        }
    }

    uint32_t ph[4][4], pl[4][4];
    #pragma unroll
    for (int kt = 0; kt < 4; kt++) {
        #pragma unroll
        for (int half = 0; half < 2; half++) {
            int nt = 2 * kt + half;
            __nv_bfloat162 H0 = __floats2bfloat162_rn(cS[nt][0], cS[nt][1]);
            __nv_bfloat162 H1 = __floats2bfloat162_rn(cS[nt][2], cS[nt][3]);
            __nv_bfloat162 L0 = __floats2bfloat162_rn(cS[nt][0] - __bfloat162float(H0.x),
                                                      cS[nt][1] - __bfloat162float(H0.y));
            __nv_bfloat162 L1 = __floats2bfloat162_rn(cS[nt][2] - __bfloat162float(H1.x),
                                                      cS[nt][3] - __bfloat162float(H1.y));
            ph[kt][half * 2 + 0] = *(uint32_t*)&H0;
            ph[kt][half * 2 + 1] = *(uint32_t*)&H1;
            pl[kt][half * 2 + 0] = *(uint32_t*)&L0;
            pl[kt][half * 2 + 1] = *(uint32_t*)&L1;
        }
    }

    float cO[4][4];
    #pragma unroll
    for (int nt = 0; nt < 4; nt++)
        #pragma unroll
        for (int c = 0; c < 4; c++) cO[nt][c] = 0.0f;

    #pragma unroll
    for (int kt = 0; kt < 4; kt++) {
        const int vrow = kt * 16 + (lane & 15);
        #pragma unroll
        for (int nt = 0; nt < 4; nt++) {
            uint32_t vh2[2], vl2[2];
            uint32_t ad = smem_u32(&sVh[vrow][nt * 8]);
            asm volatile("ldmatrix.sync.aligned.m8n8.x2.trans.shared.b16 {%0,%1},[%2];"
                         : "=r"(vh2[0]), "=r"(vh2[1]) : "r"(ad));
            ad = smem_u32(&sVl[vrow][nt * 8]);
            asm volatile("ldmatrix.sync.aligned.m8n8.x2.trans.shared.b16 {%0,%1},[%2];"
                         : "=r"(vl2[0]), "=r"(vl2[1]) : "r"(ad));
            MMA_BF16(cO[nt], ph[kt], vh2);
            MMA_BF16(cO[nt], pl[kt], vh2);
            MMA_BF16(cO[nt], ph[kt], vl2);
        }
    }

    {
        const int g0 = lane >> 2;
        const int c2 = (lane & 3) * 2;
        #pragma unroll
        for (int half = 0; half < 2; half++) {
            int r = warp * 16 + g0 + half * 8;
            int n = ((wh * 8 + (r >> 3)) << 6) + wc * 8 + (r & 7);
            size_t base = (size_t)(b * 4096 + n) * C_DIM + head * 32;
            #pragma unroll
            for (int nt = 0; nt < 4; nt++) {
                float v0 = cO[nt][half * 2 + 0];
                float v1 = cO[nt][half * 2 + 1];
                __nv_bfloat162 H = __floats2bfloat162_rn(v0, v1);
                __nv_bfloat162 L = __floats2bfloat162_rn(v0 - __bfloat162float(H.x),
                                                         v1 - __bfloat162float(H.y));
                size_t off = base + nt * 8 + c2;
                *(__nv_bfloat162*)(oh + off) = H;
                *(__nv_bfloat162*)(ol + off) = L;
            }
        }
    }
}

// ---------------------------------------------------------------------------
// Host launcher
// ---------------------------------------------------------------------------
extern "C" void kernel_launch(void* const* d_in, const int* in_sizes, int n_in,
                              void* d_out, int out_size)
{
    const float* x      = (const float*)d_in[0];
    const float* W_qkv  = (const float*)d_in[1];
    const float* b_qkv  = (const float*)d_in[2];
    const float* W_proj = (const float*)d_in[3];
    float* out = (float*)d_out;

    float *qkv;
    __nv_bfloat16 *xh, *xl, *ah, *al, *wqh, *wql, *wph, *wpl;
    cudaGetSymbolAddress((void**)&qkv, g_qkv);
    cudaGetSymbolAddress((void**)&xh,  g_xh);
    cudaGetSymbolAddress((void**)&xl,  g_xl);
    cudaGetSymbolAddress((void**)&ah,  g_ah);
    cudaGetSymbolAddress((void**)&al,  g_al);
    cudaGetSymbolAddress((void**)&wqh, g_wqh);
    cudaGetSymbolAddress((void**)&wql, g_wql);
    cudaGetSymbolAddress((void**)&wph, g_wph);
    cudaGetSymbolAddress((void**)&wpl, g_wpl);

    cudaFuncSetAttribute(gemm3_kernel,
                         cudaFuncAttributeMaxDynamicSharedMemorySize, GEMM_DYNSMEM);

    {
        int n4 = TOKENS * C_DIM / 4;
        split_kernel<<<(n4 + 255) / 256, 256>>>(x, xh, xl, n4);
        int w4 = C_DIM * QKV_DIM / 4;
        split_kernel<<<(w4 + 255) / 256, 256>>>(W_qkv, wqh, wql, w4);
        int p4 = C_DIM * C_DIM / 4;
        split_kernel<<<(p4 + 255) / 256, 256>>>(W_proj, wph, wpl, p4);
    }
    {
        dim3 grid(QKV_DIM / 128, TOKENS / 128);
        gemm3_kernel<<<grid, 128, GEMM_DYNSMEM>>>(xh, xl, wqh, wql, b_qkv, qkv,
                                                  QKV_DIM, C_DIM);
    }
    {
        dim3 grid(1024, 12);
        attn_tc_kernel<<<grid, 128>>>(qkv, ah, al);
    }
    {
        dim3 grid(C_DIM / 128, TOKENS / 128);
        gemm3_kernel<<<grid, 128, GEMM_DYNSMEM>>>(ah, al, wph, wpl, nullptr, out,
                                                  C_DIM, C_DIM);
    }
}

// round 7
// speedup vs baseline: 3.7337x; 1.0000x over previous
#include <cuda_runtime.h>
#include <cuda_bf16.h>
#include <cstdint>

// x: [16,4096,384] fp32 -> out [16,4096,384] fp32
// 8x8 window attention over 64x64 grid, 12 heads, hd=32.

#define TOKENS   65536
#define C_DIM    384
#define QKV_DIM  1152

__device__ float          g_qkv[(size_t)TOKENS * QKV_DIM];
__device__ __nv_bfloat16  g_xh [(size_t)TOKENS * C_DIM];
__device__ __nv_bfloat16  g_xl [(size_t)TOKENS * C_DIM];
__device__ __nv_bfloat16  g_ah [(size_t)TOKENS * C_DIM];
__device__ __nv_bfloat16  g_al [(size_t)TOKENS * C_DIM];
__device__ __nv_bfloat16  g_wqh[(size_t)C_DIM * QKV_DIM];
__device__ __nv_bfloat16  g_wql[(size_t)C_DIM * QKV_DIM];
__device__ __nv_bfloat16  g_wph[(size_t)C_DIM * C_DIM];
__device__ __nv_bfloat16  g_wpl[(size_t)C_DIM * C_DIM];

static __device__ __forceinline__ uint32_t smem_u32(const void* p) {
    return (uint32_t)__cvta_generic_to_shared(p);
}

#define CP_ASYNC16(smem, gptr) \
    asm volatile("cp.async.cg.shared.global [%0], [%1], 16;" :: "r"(smem), "l"(gptr))
#define CP_COMMIT() asm volatile("cp.async.commit_group;" ::: "memory")

#define MMA_BF16(d, a, b)                                                      \
    asm volatile(                                                              \
        "mma.sync.aligned.m16n8k16.row.col.f32.bf16.bf16.f32 "                 \
        "{%0,%1,%2,%3},{%4,%5,%6,%7},{%8,%9},{%0,%1,%2,%3};"                   \
        : "+f"(d[0]), "+f"(d[1]), "+f"(d[2]), "+f"(d[3])                       \
        : "r"(a[0]), "r"(a[1]), "r"(a[2]), "r"(a[3]), "r"(b[0]), "r"(b[1]))

// ---------------------------------------------------------------------------
// fp32 -> (hi, lo) bf16 split
// ---------------------------------------------------------------------------
__global__ void split_kernel(const float* __restrict__ in,
                             __nv_bfloat16* __restrict__ hi,
                             __nv_bfloat16* __restrict__ lo, int n4)
{
    int i = blockIdx.x * blockDim.x + threadIdx.x;
    if (i >= n4) return;
    float4 v = ((const float4*)in)[i];
    __nv_bfloat16 h0 = __float2bfloat16(v.x), h1 = __float2bfloat16(v.y);
    __nv_bfloat16 h2 = __float2bfloat16(v.z), h3 = __float2bfloat16(v.w);
    __nv_bfloat162* hp = (__nv_bfloat162*)hi;
    __nv_bfloat162* lp = (__nv_bfloat162*)lo;
    hp[i*2]   = __nv_bfloat162(h0, h1);
    hp[i*2+1] = __nv_bfloat162(h2, h3);
    lp[i*2]   = __nv_bfloat162(__float2bfloat16(v.x - __bfloat162float(h0)),
                               __float2bfloat16(v.y - __bfloat162float(h1)));
    lp[i*2+1] = __nv_bfloat162(__float2bfloat16(v.z - __bfloat162float(h2)),
                               __float2bfloat16(v.w - __bfloat162float(h3)));
}

// ---------------------------------------------------------------------------
// 3x-bf16-split GEMM (mma.sync m16n8k16), cp.async 3-stage pipeline,
// one __syncthreads per k-tile, dependency-broken MMA ordering.
// CTA 128x128, 4 warps (2x2), warp tile 64x64, BK=32.
// ---------------------------------------------------------------------------
#define ST_AL 10240
#define ST_BH 20480
#define ST_BL 29184
#define ST_SZ 37888
#define N_STAGES 3
#define GEMM_DYNSMEM (N_STAGES * ST_SZ)

__global__ __launch_bounds__(128, 2)
void gemm3_kernel(const __nv_bfloat16* __restrict__ Ah,
                  const __nv_bfloat16* __restrict__ Al,
                  const __nv_bfloat16* __restrict__ Bh,
                  const __nv_bfloat16* __restrict__ Bl,
                  const float* __restrict__ bias,
                  float* __restrict__ C, int N, int K)
{
    extern __shared__ char smem_raw[];
    const uint32_t sbase = smem_u32(smem_raw);

    const int tid  = threadIdx.x;
    const int lane = tid & 31;
    const int warp = tid >> 5;
    const int wm   = warp >> 1;
    const int wn   = warp & 1;
    const int m0   = blockIdx.y * 128;
    const int n0   = blockIdx.x * 128;
    const int KT   = K / 32;

    float acc[4][8][4];
    #pragma unroll
    for (int mi = 0; mi < 4; mi++)
        #pragma unroll
        for (int ni = 0; ni < 8; ni++)
            #pragma unroll
            for (int c = 0; c < 4; c++) acc[mi][ni][c] = 0.0f;

    uint32_t aso[4]; size_t ago[4];
    uint32_t bso[4]; size_t bgo[4];
    #pragma unroll
    for (int j = 0; j < 4; j++) {
        int idx = j * 128 + tid;
        int ar = idx >> 2, ac = idx & 3;
        aso[j] = (uint32_t)(ar * 80 + ac * 16);
        ago[j] = (size_t)ar * K + ac * 8;
        int br = idx >> 4, bc = idx & 15;
        bso[j] = (uint32_t)(br * 272 + bc * 16);
        bgo[j] = (size_t)br * N + bc * 8;
    }

    auto load_stage = [&](int kt, int st) {
        uint32_t b = sbase + st * ST_SZ;
        const __nv_bfloat16* pah = Ah + (size_t)m0 * K + kt * 32;
        const __nv_bfloat16* pal = Al + (size_t)m0 * K + kt * 32;
        const __nv_bfloat16* pbh = Bh + (size_t)(kt * 32) * N + n0;
        const __nv_bfloat16* pbl = Bl + (size_t)(kt * 32) * N + n0;
        #pragma unroll
        for (int j = 0; j < 4; j++) CP_ASYNC16(b + aso[j],         pah + ago[j]);
        #pragma unroll
        for (int j = 0; j < 4; j++) CP_ASYNC16(b + ST_AL + aso[j], pal + ago[j]);
        #pragma unroll
        for (int j = 0; j < 4; j++) CP_ASYNC16(b + ST_BH + bso[j], pbh + bgo[j]);
        #pragma unroll
        for (int j = 0; j < 4; j++) CP_ASYNC16(b + ST_BL + bso[j], pbl + bgo[j]);
        CP_COMMIT();
    };

    load_stage(0, 0);
    load_stage(1, 1);

    int stage = 0;
    for (int kt = 0; kt < KT; kt++) {
        if (kt + 1 < KT) {
            asm volatile("cp.async.wait_group 1;" ::: "memory");
        } else {
            asm volatile("cp.async.wait_group 0;" ::: "memory");
        }
        __syncthreads();

        if (kt + 2 < KT) {
            int st2 = stage + 2; if (st2 >= N_STAGES) st2 -= N_STAGES;
            load_stage(kt + 2, st2);
        }

        const uint32_t b = sbase + stage * ST_SZ;
        #pragma unroll
        for (int kh = 0; kh < 2; kh++) {
            uint32_t bh[8][2], bl[8][2];
            const int brow = kh * 16 + (lane & 15);
            #pragma unroll
            for (int ni = 0; ni < 8; ni++) {
                uint32_t col2 = (uint32_t)((wn * 64 + ni * 8) * 2);
                uint32_t ad = b + ST_BH + brow * 272 + col2;
                asm volatile("ldmatrix.sync.aligned.m8n8.x2.trans.shared.b16 {%0,%1},[%2];"
                             : "=r"(bh[ni][0]), "=r"(bh[ni][1]) : "r"(ad));
                ad = b + ST_BL + brow * 272 + col2;
                asm volatile("ldmatrix.sync.aligned.m8n8.x2.trans.shared.b16 {%0,%1},[%2];"
                             : "=r"(bl[ni][0]), "=r"(bl[ni][1]) : "r"(ad));
            }
            #pragma unroll
            for (int mi = 0; mi < 4; mi++) {
                const int arow = wm * 64 + mi * 16 + ((lane >> 3) & 1) * 8 + (lane & 7);
                const int acol = kh * 16 + (lane >> 4) * 8;
                uint32_t Ahf[4], Alf[4];
                uint32_t ad = b + arow * 80 + acol * 2;
                asm volatile("ldmatrix.sync.aligned.m8n8.x4.shared.b16 {%0,%1,%2,%3},[%4];"
                             : "=r"(Ahf[0]), "=r"(Ahf[1]), "=r"(Ahf[2]), "=r"(Ahf[3]) : "r"(ad));
                ad = b + ST_AL + arow * 80 + acol * 2;
                asm volatile("ldmatrix.sync.aligned.m8n8.x4.shared.b16 {%0,%1,%2,%3},[%4];"
                             : "=r"(Alf[0]), "=r"(Alf[1]), "=r"(Alf[2]), "=r"(Alf[3]) : "r"(ad));
                // Dependency-broken ordering: 8 independent accumulators
                // between consecutive writes to the same one.
                #pragma unroll
                for (int ni = 0; ni < 8; ni++) MMA_BF16(acc[mi][ni], Ahf, bh[ni]);
                #pragma unroll
                for (int ni = 0; ni < 8; ni++) MMA_BF16(acc[mi][ni], Ahf, bl[ni]);
                #pragma unroll
                for (int ni = 0; ni < 8; ni++) MMA_BF16(acc[mi][ni], Alf, bh[ni]);
            }
        }
        stage++; if (stage >= N_STAGES) stage = 0;
    }

    const int rbase = m0 + wm * 64 + (lane >> 2);
    const int cbase = n0 + wn * 64 + (lane & 3) * 2;
    #pragma unroll
    for (int ni = 0; ni < 8; ni++) {
        int c = cbase + ni * 8;
        float b0 = 0.f, b1 = 0.f;
        if (bias) { b0 = bias[c]; b1 = bias[c + 1]; }
        #pragma unroll
        for (int mi = 0; mi < 4; mi++) {
            int r = rbase + mi * 16;
            *(float2*)(C + (size_t)r * N + c) =
                make_float2(acc[mi][ni][0] + b0, acc[mi][ni][1] + b1);
            *(float2*)(C + (size_t)(r + 8) * N + c) =
                make_float2(acc[mi][ni][2] + b0, acc[mi][ni][3] + b1);
        }
    }
}

// ---------------------------------------------------------------------------
// Tensor-core window attention, dependency-broken MMA ordering.
// ---------------------------------------------------------------------------
__global__ __launch_bounds__(128)
void attn_tc_kernel(const float* __restrict__ qkv,
                    __nv_bfloat16* __restrict__ oh,
                    __nv_bfloat16* __restrict__ ol)
{
    __shared__ __nv_bfloat16 sQh[64][40], sQl[64][40];
    __shared__ __nv_bfloat16 sKh[64][40], sKl[64][40];
    __shared__ __nv_bfloat16 sVh[64][40], sVl[64][40];

    const int wx   = blockIdx.x;
    const int head = blockIdx.y;
    const int b  = wx >> 6;
    const int wi = wx & 63;
    const int wh = wi >> 3;
    const int wc = wi & 7;
    const int tid  = threadIdx.x;
    const int lane = tid & 31;
    const int warp = tid >> 5;

    #pragma unroll
    for (int i = 0; i < 4; i++) {
        int f  = i * 128 + tid;
        int r  = f >> 3;
        int c4 = f & 7;
        int n = ((wh * 8 + (r >> 3)) << 6) + wc * 8 + (r & 7);
        const float* row = qkv + (size_t)(b * 4096 + n) * QKV_DIM + head * 32;
        float4 qv = *(const float4*)(row + c4 * 4);
        float4 kv = *(const float4*)(row + 384 + c4 * 4);
        float4 vv = *(const float4*)(row + 768 + c4 * 4);
        #pragma unroll
        for (int m = 0; m < 3; m++) {
            float4 v = (m == 0) ? qv : (m == 1) ? kv : vv;
            __nv_bfloat162 H0 = __floats2bfloat162_rn(v.x, v.y);
            __nv_bfloat162 H1 = __floats2bfloat162_rn(v.z, v.w);
            __nv_bfloat162 L0 = __floats2bfloat162_rn(v.x - __bfloat162float(H0.x),
                                                      v.y - __bfloat162float(H0.y));
            __nv_bfloat162 L1 = __floats2bfloat162_rn(v.z - __bfloat162float(H1.x),
                                                      v.w - __bfloat162float(H1.y));
            __nv_bfloat16* ph = (m == 0) ? &sQh[r][c4*4] : (m == 1) ? &sKh[r][c4*4] : &sVh[r][c4*4];
            __nv_bfloat16* pl = (m == 0) ? &sQl[r][c4*4] : (m == 1) ? &sKl[r][c4*4] : &sVl[r][c4*4];
            *(__nv_bfloat162*)(ph)     = H0;
            *(__nv_bfloat162*)(ph + 2) = H1;
            *(__nv_bfloat162*)(pl)     = L0;
            *(__nv_bfloat162*)(pl + 2) = L1;
        }
    }
    __syncthreads();

    float cS[8][4];
    #pragma unroll
    for (int nt = 0; nt < 8; nt++)
        #pragma unroll
        for (int c = 0; c < 4; c++) cS[nt][c] = 0.0f;

    #pragma unroll
    for (int kt = 0; kt < 2; kt++) {
        const int arow = warp * 16 + ((lane >> 3) & 1) * 8 + (lane & 7);
        const int acol = kt * 16 + (lane >> 4) * 8;
        uint32_t qh[4], ql[4];
        uint32_t ad = smem_u32(&sQh[arow][acol]);
        asm volatile("ldmatrix.sync.aligned.m8n8.x4.shared.b16 {%0,%1,%2,%3},[%4];"
                     : "=r"(qh[0]), "=r"(qh[1]), "=r"(qh[2]), "=r"(qh[3]) : "r"(ad));
        ad = smem_u32(&sQl[arow][acol]);
        asm volatile("ldmatrix.sync.aligned.m8n8.x4.shared.b16 {%0,%1,%2,%3},[%4];"
                     : "=r"(ql[0]), "=r"(ql[1]), "=r"(ql[2]), "=r"(ql[3]) : "r"(ad));
        uint32_t kh2[8][2], kl2[8][2];
        #pragma unroll
        for (int nt = 0; nt < 8; nt++) {
            const int brow = nt * 8 + (lane & 7);
            const int bcol = kt * 16 + ((lane >> 3) & 1) * 8;
            uint32_t bd = smem_u32(&sKh[brow][bcol]);
            asm volatile("ldmatrix.sync.aligned.m8n8.x2.shared.b16 {%0,%1},[%2];"
                         : "=r"(kh2[nt][0]), "=r"(kh2[nt][1]) : "r"(bd));
            bd = smem_u32(&sKl[brow][bcol]);
            asm volatile("ldmatrix.sync.aligned.m8n8.x2.shared.b16 {%0,%1},[%2];"
                         : "=r"(kl2[nt][0]), "=r"(kl2[nt][1]) : "r"(bd));
        }
        #pragma unroll
        for (int nt = 0; nt < 8; nt++) MMA_BF16(cS[nt], qh, kh2[nt]);
        #pragma unroll
        for (int nt = 0; nt < 8; nt++) MMA_BF16(cS[nt], ql, kh2[nt]);
        #pragma unroll
        for (int nt = 0; nt < 8; nt++) MMA_BF16(cS[nt], qh, kl2[nt]);
    }

    const float scale = 0.17677669529663687f;
    {
        float m0 = -1e30f, m1 = -1e30f;
        #pragma unroll
        for (int nt = 0; nt < 8; nt++) {
            m0 = fmaxf(m0, fmaxf(cS[nt][0], cS[nt][1]));
            m1 = fmaxf(m1, fmaxf(cS[nt][2], cS[nt][3]));
        }
        m0 = fmaxf(m0, __shfl_xor_sync(0xffffffffu, m0, 1));
        m0 = fmaxf(m0, __shfl_xor_sync(0xffffffffu, m0, 2));
        m1 = fmaxf(m1, __shfl_xor_sync(0xffffffffu, m1, 1));
        m1 = fmaxf(m1, __shfl_xor_sync(0xffffffffu, m1, 2));
        float s0 = 0.f, s1 = 0.f;
        #pragma unroll
        for (int nt = 0; nt < 8; nt++) {
            cS[nt][0] = __expf((cS[nt][0] - m0) * scale); s0 += cS[nt][0];
            cS[nt][1] = __expf((cS[nt][1] - m0) * scale); s0 += cS[nt][1];
            cS[nt][2] = __expf((cS[nt][2] - m1) * scale); s1 += cS[nt][2];
            cS[nt][3] = __expf((cS[nt][3] - m1) * scale); s1 += cS[nt][3];
        }
        s0 += __shfl_xor_sync(0xffffffffu, s0, 1);
        s0 += __shfl_xor_sync(0xffffffffu, s0, 2);
        s1 += __shfl_xor_sync(0xffffffffu, s1, 1);
        s1 += __shfl_xor_sync(0xffffffffu, s1, 2);
        float i0 = 1.0f / s0, i1 = 1.0f / s1;
        #pragma unroll
        for (int nt = 0; nt < 8; nt++) {
            cS[nt][0] *= i0; cS[nt][1] *= i0;
            cS[nt][2] *= i1; cS[nt][3] *= i1;
        }
    }

    uint32_t ph[4][4], pl[4][4];
    #pragma unroll
    for (int kt = 0; kt < 4; kt++) {
        #pragma unroll
        for (int half = 0; half < 2; half++) {
            int nt = 2 * kt + half;
            __nv_bfloat162 H0 = __floats2bfloat162_rn(cS[nt][0], cS[nt][1]);
            __nv_bfloat162 H1 = __floats2bfloat162_rn(cS[nt][2], cS[nt][3]);
            __nv_bfloat162 L0 = __floats2bfloat162_rn(cS[nt][0] - __bfloat162float(H0.x),
                                                      cS[nt][1] - __bfloat162float(H0.y));
            __nv_bfloat162 L1 = __floats2bfloat162_rn(cS[nt][2] - __bfloat162float(H1.x),
                                                      cS[nt][3] - __bfloat162float(H1.y));
            ph[kt][half * 2 + 0] = *(uint32_t*)&H0;
            ph[kt][half * 2 + 1] = *(uint32_t*)&H1;
            pl[kt][half * 2 + 0] = *(uint32_t*)&L0;
            pl[kt][half * 2 + 1] = *(uint32_t*)&L1;
        }
    }

    float cO[4][4];
    #pragma unroll
    for (int nt = 0; nt < 4; nt++)
        #pragma unroll
        for (int c = 0; c < 4; c++) cO[nt][c] = 0.0f;

    #pragma unroll
    for (int kt = 0; kt < 4; kt++) {
        const int vrow = kt * 16 + (lane & 15);
        uint32_t vh2[4][2], vl2[4][2];
        #pragma unroll
        for (int nt = 0; nt < 4; nt++) {
            uint32_t ad = smem_u32(&sVh[vrow][nt * 8]);
            asm volatile("ldmatrix.sync.aligned.m8n8.x2.trans.shared.b16 {%0,%1},[%2];"
                         : "=r"(vh2[nt][0]), "=r"(vh2[nt][1]) : "r"(ad));
            ad = smem_u32(&sVl[vrow][nt * 8]);
            asm volatile("ldmatrix.sync.aligned.m8n8.x2.trans.shared.b16 {%0,%1},[%2];"
                         : "=r"(vl2[nt][0]), "=r"(vl2[nt][1]) : "r"(ad));
        }
        #pragma unroll
        for (int nt = 0; nt < 4; nt++) MMA_BF16(cO[nt], ph[kt], vh2[nt]);
        #pragma unroll
        for (int nt = 0; nt < 4; nt++) MMA_BF16(cO[nt], pl[kt], vh2[nt]);
        #pragma unroll
        for (int nt = 0; nt < 4; nt++) MMA_BF16(cO[nt], ph[kt], vl2[nt]);
    }

    {
        const int g0 = lane >> 2;
        const int c2 = (lane & 3) * 2;
        #pragma unroll
        for (int half = 0; half < 2; half++) {
            int r = warp * 16 + g0 + half * 8;
            int n = ((wh * 8 + (r >> 3)) << 6) + wc * 8 + (r & 7);
            size_t base = (size_t)(b * 4096 + n) * C_DIM + head * 32;
            #pragma unroll
            for (int nt = 0; nt < 4; nt++) {
                float v0 = cO[nt][half * 2 + 0];
                float v1 = cO[nt][half * 2 + 1];
                __nv_bfloat162 H = __floats2bfloat162_rn(v0, v1);
                __nv_bfloat162 L = __floats2bfloat162_rn(v0 - __bfloat162float(H.x),
                                                         v1 - __bfloat162float(H.y));
                size_t off = base + nt * 8 + c2;
                *(__nv_bfloat162*)(oh + off) = H;
                *(__nv_bfloat162*)(ol + off) = L;
            }
        }
    }
}

// ---------------------------------------------------------------------------
// Host launcher
// ---------------------------------------------------------------------------
extern "C" void kernel_launch(void* const* d_in, const int* in_sizes, int n_in,
                              void* d_out, int out_size)
{
    const float* x      = (const float*)d_in[0];
    const float* W_qkv  = (const float*)d_in[1];
    const float* b_qkv  = (const float*)d_in[2];
    const float* W_proj = (const float*)d_in[3];
    float* out = (float*)d_out;

    float *qkv;
    __nv_bfloat16 *xh, *xl, *ah, *al, *wqh, *wql, *wph, *wpl;
    cudaGetSymbolAddress((void**)&qkv, g_qkv);
    cudaGetSymbolAddress((void**)&xh,  g_xh);
    cudaGetSymbolAddress((void**)&xl,  g_xl);
    cudaGetSymbolAddress((void**)&ah,  g_ah);
    cudaGetSymbolAddress((void**)&al,  g_al);
    cudaGetSymbolAddress((void**)&wqh, g_wqh);
    cudaGetSymbolAddress((void**)&wql, g_wql);
    cudaGetSymbolAddress((void**)&wph, g_wph);
    cudaGetSymbolAddress((void**)&wpl, g_wpl);

    cudaFuncSetAttribute(gemm3_kernel,
                         cudaFuncAttributeMaxDynamicSharedMemorySize, GEMM_DYNSMEM);

    {
        int n4 = TOKENS * C_DIM / 4;
        split_kernel<<<(n4 + 255) / 256, 256>>>(x, xh, xl, n4);
        int w4 = C_DIM * QKV_DIM / 4;
        split_kernel<<<(w4 + 255) / 256, 256>>>(W_qkv, wqh, wql, w4);
        int p4 = C_DIM * C_DIM / 4;
        split_kernel<<<(p4 + 255) / 256, 256>>>(W_proj, wph, wpl, p4);
    }
    {
        dim3 grid(QKV_DIM / 128, TOKENS / 128);
        gemm3_kernel<<<grid, 128, GEMM_DYNSMEM>>>(xh, xl, wqh, wql, b_qkv, qkv,
                                                  QKV_DIM, C_DIM);
    }
    {
        dim3 grid(1024, 12);
        attn_tc_kernel<<<grid, 128>>>(qkv, ah, al);
    }
    {
        dim3 grid(C_DIM / 128, TOKENS / 128);
        gemm3_kernel<<<grid, 128, GEMM_DYNSMEM>>>(ah, al, wph, wpl, nullptr, out,
                                                  C_DIM, C_DIM);
    }
}

// round 9
// speedup vs baseline: 3.8697x; 1.0364x over previous
#include <cuda_runtime.h>
#include <cuda_bf16.h>
#include <cstdint>

// x: [16,4096,384] fp32 -> out [16,4096,384] fp32
// 8x8 window attention over 64x64 grid, 12 heads, hd=32.

#define TOKENS   65536
#define C_DIM    384
#define QKV_DIM  1152

__device__ float          g_qkv[(size_t)TOKENS * QKV_DIM];
__device__ __nv_bfloat16  g_ah [(size_t)TOKENS * C_DIM];
__device__ __nv_bfloat16  g_al [(size_t)TOKENS * C_DIM];
__device__ __nv_bfloat16  g_wqh[(size_t)C_DIM * QKV_DIM];
__device__ __nv_bfloat16  g_wql[(size_t)C_DIM * QKV_DIM];
__device__ __nv_bfloat16  g_wph[(size_t)C_DIM * C_DIM];
__device__ __nv_bfloat16  g_wpl[(size_t)C_DIM * C_DIM];

static __device__ __forceinline__ uint32_t smem_u32(const void* p) {
    return (uint32_t)__cvta_generic_to_shared(p);
}

#define CP_ASYNC16(smem, gptr) \
    asm volatile("cp.async.cg.shared.global [%0], [%1], 16;" :: "r"(smem), "l"(gptr))
#define CP_COMMIT() asm volatile("cp.async.commit_group;" ::: "memory")

#define MMA_BF16(d, a, b)                                                      \
    asm volatile(                                                              \
        "mma.sync.aligned.m16n8k16.row.col.f32.bf16.bf16.f32 "                 \
        "{%0,%1,%2,%3},{%4,%5,%6,%7},{%8,%9},{%0,%1,%2,%3};"                   \
        : "+f"(d[0]), "+f"(d[1]), "+f"(d[2]), "+f"(d[3])                       \
        : "r"(a[0]), "r"(a[1]), "r"(a[2]), "r"(a[3]), "r"(b[0]), "r"(b[1]))

// ---------------------------------------------------------------------------
// fp32 -> (hi, lo) bf16 split (weights only now)
// ---------------------------------------------------------------------------
__global__ void split_kernel(const float* __restrict__ in,
                             __nv_bfloat16* __restrict__ hi,
                             __nv_bfloat16* __restrict__ lo, int n4)
{
    int i = blockIdx.x * blockDim.x + threadIdx.x;
    if (i >= n4) return;
    float4 v = ((const float4*)in)[i];
    __nv_bfloat16 h0 = __float2bfloat16(v.x), h1 = __float2bfloat16(v.y);
    __nv_bfloat16 h2 = __float2bfloat16(v.z), h3 = __float2bfloat16(v.w);
    __nv_bfloat162* hp = (__nv_bfloat162*)hi;
    __nv_bfloat162* lp = (__nv_bfloat162*)lo;
    hp[i*2]   = __nv_bfloat162(h0, h1);
    hp[i*2+1] = __nv_bfloat162(h2, h3);
    lp[i*2]   = __nv_bfloat162(__float2bfloat16(v.x - __bfloat162float(h0)),
                               __float2bfloat16(v.y - __bfloat162float(h1)));
    lp[i*2+1] = __nv_bfloat162(__float2bfloat16(v.z - __bfloat162float(h2)),
                               __float2bfloat16(v.w - __bfloat162float(h3)));
}

// ---------------------------------------------------------------------------
// Fused-split GEMM for QKV: A is fp32 (x), split to bf16 hi/lo IN-KERNEL.
// C = Ah@Bh + Ah@Bl + Al@Bh + bias.  CTA 128x128, 4 warps (2x2), warp 64x64,
// BK=32, 2-stage cp.async (A fp32 staging + B bf16 hi/lo).
//
// smem layout (bytes):
//   AF32 staging: 2 stages x 128 rows x 144B          @ 0      (36864)
//   ABh:          128 x 80B (single buffer)            @ 36864  (10240)
//   ABl:                                               @ 47104  (10240)
//   B stages:     2 x (Bh 32x272 + Bl 32x272)          @ 57344  (2x17408)
//   total 92160 -> 2 CTAs/SM
// ---------------------------------------------------------------------------
#define FA_AF32   0
#define FA_AF32_ST 18432
#define FA_ABH    36864
#define FA_ABL    47104
#define FA_B      57344
#define FA_B_ST   17408
#define FA_BL_OFF 8704
#define FA_DYNSMEM 92160

__global__ __launch_bounds__(128, 2)
void gemm3_qkv_kernel(const float* __restrict__ A,
                      const __nv_bfloat16* __restrict__ Bh,
                      const __nv_bfloat16* __restrict__ Bl,
                      const float* __restrict__ bias,
                      float* __restrict__ C, int N, int K)
{
    extern __shared__ char smem_raw[];
    const uint32_t sbase = smem_u32(smem_raw);

    const int tid  = threadIdx.x;
    const int lane = tid & 31;
    const int warp = tid >> 5;
    const int wm   = warp >> 1;
    const int wn   = warp & 1;
    const int m0   = blockIdx.y * 128;
    const int n0   = blockIdx.x * 128;
    const int KT   = K / 32;

    float acc[4][8][4];
    #pragma unroll
    for (int mi = 0; mi < 4; mi++)
        #pragma unroll
        for (int ni = 0; ni < 8; ni++)
            #pragma unroll
            for (int c = 0; c < 4; c++) acc[mi][ni][c] = 0.0f;

    // cp.async offsets: A fp32 (8 chunks/thread), B hi/lo (4 each)
    uint32_t afo[8]; size_t afg[8];
    #pragma unroll
    for (int j = 0; j < 8; j++) {
        int idx = j * 128 + tid;        // 0..1023
        int r = idx >> 3, c = idx & 7;  // row 0..127, 16B chunk 0..7
        afo[j] = (uint32_t)(r * 144 + c * 16);
        afg[j] = (size_t)r * K + c * 4; // floats
    }
    uint32_t bso[4]; size_t bgo[4];
    #pragma unroll
    for (int j = 0; j < 4; j++) {
        int idx = j * 128 + tid;
        int br = idx >> 4, bc = idx & 15;
        bso[j] = (uint32_t)(br * 272 + bc * 16);
        bgo[j] = (size_t)br * N + bc * 8;
    }

    auto load_stage = [&](int kt, int st) {
        uint32_t ab = sbase + FA_AF32 + st * FA_AF32_ST;
        const float* pa = A + (size_t)m0 * K + kt * 32;
        #pragma unroll
        for (int j = 0; j < 8; j++) CP_ASYNC16(ab + afo[j], pa + afg[j]);
        uint32_t bb = sbase + FA_B + st * FA_B_ST;
        const __nv_bfloat16* pbh = Bh + (size_t)(kt * 32) * N + n0;
        const __nv_bfloat16* pbl = Bl + (size_t)(kt * 32) * N + n0;
        #pragma unroll
        for (int j = 0; j < 4; j++) CP_ASYNC16(bb + bso[j],             pbh + bgo[j]);
        #pragma unroll
        for (int j = 0; j < 4; j++) CP_ASYNC16(bb + FA_BL_OFF + bso[j], pbl + bgo[j]);
        CP_COMMIT();
    };

    load_stage(0, 0);

    for (int kt = 0; kt < KT; kt++) {
        const int st = kt & 1;
        asm volatile("cp.async.wait_group 0;" ::: "memory");
        __syncthreads();                 // staging ready + prior MMAs done

        if (kt + 1 < KT) load_stage(kt + 1, st ^ 1);

        // Convert A fp32 staging -> single bf16 hi/lo buffer (row = tid)
        {
            const float* arow = (const float*)(smem_raw + FA_AF32 + st * FA_AF32_ST
                                               + tid * 144);
            __nv_bfloat16* hrow = (__nv_bfloat16*)(smem_raw + FA_ABH + tid * 80);
            __nv_bfloat16* lrow = (__nv_bfloat16*)(smem_raw + FA_ABL + tid * 80);
            #pragma unroll
            for (int j = 0; j < 8; j++) {
                float4 v = *(const float4*)(arow + j * 4);
                __nv_bfloat162 H0 = __floats2bfloat162_rn(v.x, v.y);
                __nv_bfloat162 H1 = __floats2bfloat162_rn(v.z, v.w);
                __nv_bfloat162 L0 = __floats2bfloat162_rn(v.x - __bfloat162float(H0.x),
                                                          v.y - __bfloat162float(H0.y));
                __nv_bfloat162 L1 = __floats2bfloat162_rn(v.z - __bfloat162float(H1.x),
                                                          v.w - __bfloat162float(H1.y));
                *(__nv_bfloat162*)(hrow + j * 4)     = H0;
                *(__nv_bfloat162*)(hrow + j * 4 + 2) = H1;
                *(__nv_bfloat162*)(lrow + j * 4)     = L0;
                *(__nv_bfloat162*)(lrow + j * 4 + 2) = L1;
            }
        }
        __syncthreads();                 // A bf16 ready

        const uint32_t bb = sbase + FA_B + st * FA_B_ST;
        #pragma unroll
        for (int kh = 0; kh < 2; kh++) {
            uint32_t bh[8][2], bl[8][2];
            const int brow = kh * 16 + (lane & 15);
            #pragma unroll
            for (int ni = 0; ni < 8; ni++) {
                uint32_t col2 = (uint32_t)((wn * 64 + ni * 8) * 2);
                uint32_t ad = bb + brow * 272 + col2;
                asm volatile("ldmatrix.sync.aligned.m8n8.x2.trans.shared.b16 {%0,%1},[%2];"
                             : "=r"(bh[ni][0]), "=r"(bh[ni][1]) : "r"(ad));
                ad = bb + FA_BL_OFF + brow * 272 + col2;
                asm volatile("ldmatrix.sync.aligned.m8n8.x2.trans.shared.b16 {%0,%1},[%2];"
                             : "=r"(bl[ni][0]), "=r"(bl[ni][1]) : "r"(ad));
            }
            #pragma unroll
            for (int mi = 0; mi < 4; mi++) {
                const int arow = wm * 64 + mi * 16 + ((lane >> 3) & 1) * 8 + (lane & 7);
                const int acol = kh * 16 + (lane >> 4) * 8;
                uint32_t Ahf[4], Alf[4];
                uint32_t ad = sbase + FA_ABH + arow * 80 + acol * 2;
                asm volatile("ldmatrix.sync.aligned.m8n8.x4.shared.b16 {%0,%1,%2,%3},[%4];"
                             : "=r"(Ahf[0]), "=r"(Ahf[1]), "=r"(Ahf[2]), "=r"(Ahf[3]) : "r"(ad));
                ad = sbase + FA_ABL + arow * 80 + acol * 2;
                asm volatile("ldmatrix.sync.aligned.m8n8.x4.shared.b16 {%0,%1,%2,%3},[%4];"
                             : "=r"(Alf[0]), "=r"(Alf[1]), "=r"(Alf[2]), "=r"(Alf[3]) : "r"(ad));
                #pragma unroll
                for (int ni = 0; ni < 8; ni++) MMA_BF16(acc[mi][ni], Ahf, bh[ni]);
                #pragma unroll
                for (int ni = 0; ni < 8; ni++) MMA_BF16(acc[mi][ni], Ahf, bl[ni]);
                #pragma unroll
                for (int ni = 0; ni < 8; ni++) MMA_BF16(acc[mi][ni], Alf, bh[ni]);
            }
        }
    }

    const int rbase = m0 + wm * 64 + (lane >> 2);
    const int cbase = n0 + wn * 64 + (lane & 3) * 2;
    #pragma unroll
    for (int ni = 0; ni < 8; ni++) {
        int c = cbase + ni * 8;
        float b0 = bias[c], b1 = bias[c + 1];
        #pragma unroll
        for (int mi = 0; mi < 4; mi++) {
            int r = rbase + mi * 16;
            *(float2*)(C + (size_t)r * N + c) =
                make_float2(acc[mi][ni][0] + b0, acc[mi][ni][1] + b1);
            *(float2*)(C + (size_t)(r + 8) * N + c) =
                make_float2(acc[mi][ni][2] + b0, acc[mi][ni][3] + b1);
        }
    }
}

// ---------------------------------------------------------------------------
// bf16-A 3x-split GEMM (proj): unchanged.
// ---------------------------------------------------------------------------
#define ST_AL 10240
#define ST_BH 20480
#define ST_BL 29184
#define ST_SZ 37888
#define N_STAGES 3
#define GEMM_DYNSMEM (N_STAGES * ST_SZ)

__global__ __launch_bounds__(128, 2)
void gemm3_kernel(const __nv_bfloat16* __restrict__ Ah,
                  const __nv_bfloat16* __restrict__ Al,
                  const __nv_bfloat16* __restrict__ Bh,
                  const __nv_bfloat16* __restrict__ Bl,
                  const float* __restrict__ bias,
                  float* __restrict__ C, int N, int K)
{
    extern __shared__ char smem_raw[];
    const uint32_t sbase = smem_u32(smem_raw);

    const int tid  = threadIdx.x;
    const int lane = tid & 31;
    const int warp = tid >> 5;
    const int wm   = warp >> 1;
    const int wn   = warp & 1;
    const int m0   = blockIdx.y * 128;
    const int n0   = blockIdx.x * 128;
    const int KT   = K / 32;

    float acc[4][8][4];
    #pragma unroll
    for (int mi = 0; mi < 4; mi++)
        #pragma unroll
        for (int ni = 0; ni < 8; ni++)
            #pragma unroll
            for (int c = 0; c < 4; c++) acc[mi][ni][c] = 0.0f;

    uint32_t aso[4]; size_t ago[4];
    uint32_t bso[4]; size_t bgo[4];
    #pragma unroll
    for (int j = 0; j < 4; j++) {
        int idx = j * 128 + tid;
        int ar = idx >> 2, ac = idx & 3;
        aso[j] = (uint32_t)(ar * 80 + ac * 16);
        ago[j] = (size_t)ar * K + ac * 8;
        int br = idx >> 4, bc = idx & 15;
        bso[j] = (uint32_t)(br * 272 + bc * 16);
        bgo[j] = (size_t)br * N + bc * 8;
    }

    auto load_stage = [&](int kt, int st) {
        uint32_t b = sbase + st * ST_SZ;
        const __nv_bfloat16* pah = Ah + (size_t)m0 * K + kt * 32;
        const __nv_bfloat16* pal = Al + (size_t)m0 * K + kt * 32;
        const __nv_bfloat16* pbh = Bh + (size_t)(kt * 32) * N + n0;
        const __nv_bfloat16* pbl = Bl + (size_t)(kt * 32) * N + n0;
        #pragma unroll
        for (int j = 0; j < 4; j++) CP_ASYNC16(b + aso[j],         pah + ago[j]);
        #pragma unroll
        for (int j = 0; j < 4; j++) CP_ASYNC16(b + ST_AL + aso[j], pal + ago[j]);
        #pragma unroll
        for (int j = 0; j < 4; j++) CP_ASYNC16(b + ST_BH + bso[j], pbh + bgo[j]);
        #pragma unroll
        for (int j = 0; j < 4; j++) CP_ASYNC16(b + ST_BL + bso[j], pbl + bgo[j]);
        CP_COMMIT();
    };

    load_stage(0, 0);
    load_stage(1, 1);

    int stage = 0;
    for (int kt = 0; kt < KT; kt++) {
        if (kt + 1 < KT) {
            asm volatile("cp.async.wait_group 1;" ::: "memory");
        } else {
            asm volatile("cp.async.wait_group 0;" ::: "memory");
        }
        __syncthreads();

        if (kt + 2 < KT) {
            int st2 = stage + 2; if (st2 >= N_STAGES) st2 -= N_STAGES;
            load_stage(kt + 2, st2);
        }

        const uint32_t b = sbase + stage * ST_SZ;
        #pragma unroll
        for (int kh = 0; kh < 2; kh++) {
            uint32_t bh[8][2], bl[8][2];
            const int brow = kh * 16 + (lane & 15);
            #pragma unroll
            for (int ni = 0; ni < 8; ni++) {
                uint32_t col2 = (uint32_t)((wn * 64 + ni * 8) * 2);
                uint32_t ad = b + ST_BH + brow * 272 + col2;
                asm volatile("ldmatrix.sync.aligned.m8n8.x2.trans.shared.b16 {%0,%1},[%2];"
                             : "=r"(bh[ni][0]), "=r"(bh[ni][1]) : "r"(ad));
                ad = b + ST_BL + brow * 272 + col2;
                asm volatile("ldmatrix.sync.aligned.m8n8.x2.trans.shared.b16 {%0,%1},[%2];"
                             : "=r"(bl[ni][0]), "=r"(bl[ni][1]) : "r"(ad));
            }
            #pragma unroll
            for (int mi = 0; mi < 4; mi++) {
                const int arow = wm * 64 + mi * 16 + ((lane >> 3) & 1) * 8 + (lane & 7);
                const int acol = kh * 16 + (lane >> 4) * 8;
                uint32_t Ahf[4], Alf[4];
                uint32_t ad = b + arow * 80 + acol * 2;
                asm volatile("ldmatrix.sync.aligned.m8n8.x4.shared.b16 {%0,%1,%2,%3},[%4];"
                             : "=r"(Ahf[0]), "=r"(Ahf[1]), "=r"(Ahf[2]), "=r"(Ahf[3]) : "r"(ad));
                ad = b + ST_AL + arow * 80 + acol * 2;
                asm volatile("ldmatrix.sync.aligned.m8n8.x4.shared.b16 {%0,%1,%2,%3},[%4];"
                             : "=r"(Alf[0]), "=r"(Alf[1]), "=r"(Alf[2]), "=r"(Alf[3]) : "r"(ad));
                #pragma unroll
                for (int ni = 0; ni < 8; ni++) MMA_BF16(acc[mi][ni], Ahf, bh[ni]);
                #pragma unroll
                for (int ni = 0; ni < 8; ni++) MMA_BF16(acc[mi][ni], Ahf, bl[ni]);
                #pragma unroll
                for (int ni = 0; ni < 8; ni++) MMA_BF16(acc[mi][ni], Alf, bh[ni]);
            }
        }
        stage++; if (stage >= N_STAGES) stage = 0;
    }

    const int rbase = m0 + wm * 64 + (lane >> 2);
    const int cbase = n0 + wn * 64 + (lane & 3) * 2;
    #pragma unroll
    for (int ni = 0; ni < 8; ni++) {
        int c = cbase + ni * 8;
        float b0 = 0.f, b1 = 0.f;
        if (bias) { b0 = bias[c]; b1 = bias[c + 1]; }
        #pragma unroll
        for (int mi = 0; mi < 4; mi++) {
            int r = rbase + mi * 16;
            *(float2*)(C + (size_t)r * N + c) =
                make_float2(acc[mi][ni][0] + b0, acc[mi][ni][1] + b1);
            *(float2*)(C + (size_t)(r + 8) * N + c) =
                make_float2(acc[mi][ni][2] + b0, acc[mi][ni][3] + b1);
        }
    }
}

// ---------------------------------------------------------------------------
// Tensor-core window attention (unchanged).
// ---------------------------------------------------------------------------
__global__ __launch_bounds__(128)
void attn_tc_kernel(const float* __restrict__ qkv,
                    __nv_bfloat16* __restrict__ oh,
                    __nv_bfloat16* __restrict__ ol)
{
    __shared__ __nv_bfloat16 sQh[64][40], sQl[64][40];
    __shared__ __nv_bfloat16 sKh[64][40], sKl[64][40];
    __shared__ __nv_bfloat16 sVh[64][40], sVl[64][40];

    const int wx   = blockIdx.x;
    const int head = blockIdx.y;
    const int b  = wx >> 6;
    const int wi = wx & 63;
    const int wh = wi >> 3;
    const int wc = wi & 7;
    const int tid  = threadIdx.x;
    const int lane = tid & 31;
    const int warp = tid >> 5;

    #pragma unroll
    for (int i = 0; i < 4; i++) {
        int f  = i * 128 + tid;
        int r  = f >> 3;
        int c4 = f & 7;
        int n = ((wh * 8 + (r >> 3)) << 6) + wc * 8 + (r & 7);
        const float* row = qkv + (size_t)(b * 4096 + n) * QKV_DIM + head * 32;
        float4 qv = *(const float4*)(row + c4 * 4);
        float4 kv = *(const float4*)(row + 384 + c4 * 4);
        float4 vv = *(const float4*)(row + 768 + c4 * 4);
        #pragma unroll
        for (int m = 0; m < 3; m++) {
            float4 v = (m == 0) ? qv : (m == 1) ? kv : vv;
            __nv_bfloat162 H0 = __floats2bfloat162_rn(v.x, v.y);
            __nv_bfloat162 H1 = __floats2bfloat162_rn(v.z, v.w);
            __nv_bfloat162 L0 = __floats2bfloat162_rn(v.x - __bfloat162float(H0.x),
                                                      v.y - __bfloat162float(H0.y));
            __nv_bfloat162 L1 = __floats2bfloat162_rn(v.z - __bfloat162float(H1.x),
                                                      v.w - __bfloat162float(H1.y));
            __nv_bfloat16* ph = (m == 0) ? &sQh[r][c4*4] : (m == 1) ? &sKh[r][c4*4] : &sVh[r][c4*4];
            __nv_bfloat16* pl = (m == 0) ? &sQl[r][c4*4] : (m == 1) ? &sKl[r][c4*4] : &sVl[r][c4*4];
            *(__nv_bfloat162*)(ph)     = H0;
            *(__nv_bfloat162*)(ph + 2) = H1;
            *(__nv_bfloat162*)(pl)     = L0;
            *(__nv_bfloat162*)(pl + 2) = L1;
        }
    }
    __syncthreads();

    float cS[8][4];
    #pragma unroll
    for (int nt = 0; nt < 8; nt++)
        #pragma unroll
        for (int c = 0; c < 4; c++) cS[nt][c] = 0.0f;

    #pragma unroll
    for (int kt = 0; kt < 2; kt++) {
        const int arow = warp * 16 + ((lane >> 3) & 1) * 8 + (lane & 7);
        const int acol = kt * 16 + (lane >> 4) * 8;
        uint32_t qh[4], ql[4];
        uint32_t ad = smem_u32(&sQh[arow][acol]);
        asm volatile("ldmatrix.sync.aligned.m8n8.x4.shared.b16 {%0,%1,%2,%3},[%4];"
                     : "=r"(qh[0]), "=r"(qh[1]), "=r"(qh[2]), "=r"(qh[3]) : "r"(ad));
        ad = smem_u32(&sQl[arow][acol]);
        asm volatile("ldmatrix.sync.aligned.m8n8.x4.shared.b16 {%0,%1,%2,%3},[%4];"
                     : "=r"(ql[0]), "=r"(ql[1]), "=r"(ql[2]), "=r"(ql[3]) : "r"(ad));
        uint32_t kh2[8][2], kl2[8][2];
        #pragma unroll
        for (int nt = 0; nt < 8; nt++) {
            const int brow = nt * 8 + (lane & 7);
            const int bcol = kt * 16 + ((lane >> 3) & 1) * 8;
            uint32_t bd = smem_u32(&sKh[brow][bcol]);
            asm volatile("ldmatrix.sync.aligned.m8n8.x2.shared.b16 {%0,%1},[%2];"
                         : "=r"(kh2[nt][0]), "=r"(kh2[nt][1]) : "r"(bd));
            bd = smem_u32(&sKl[brow][bcol]);
            asm volatile("ldmatrix.sync.aligned.m8n8.x2.shared.b16 {%0,%1},[%2];"
                         : "=r"(kl2[nt][0]), "=r"(kl2[nt][1]) : "r"(bd));
        }
        #pragma unroll
        for (int nt = 0; nt < 8; nt++) MMA_BF16(cS[nt], qh, kh2[nt]);
        #pragma unroll
        for (int nt = 0; nt < 8; nt++) MMA_BF16(cS[nt], ql, kh2[nt]);
        #pragma unroll
        for (int nt = 0; nt < 8; nt++) MMA_BF16(cS[nt], qh, kl2[nt]);
    }

    const float scale = 0.17677669529663687f;
    {
        float m0 = -1e30f, m1 = -1e30f;
        #pragma unroll
        for (int nt = 0; nt < 8; nt++) {
            m0 = fmaxf(m0, fmaxf(cS[nt][0], cS[nt][1]));
            m1 = fmaxf(m1, fmaxf(cS[nt][2], cS[nt][3]));
        }
        m0 = fmaxf(m0, __shfl_xor_sync(0xffffffffu, m0, 1));
        m0 = fmaxf(m0, __shfl_xor_sync(0xffffffffu, m0, 2));
        m1 = fmaxf(m1, __shfl_xor_sync(0xffffffffu, m1, 1));
        m1 = fmaxf(m1, __shfl_xor_sync(0xffffffffu, m1, 2));
        float s0 = 0.f, s1 = 0.f;
        #pragma unroll
        for (int nt = 0; nt < 8; nt++) {
            cS[nt][0] = __expf((cS[nt][0] - m0) * scale); s0 += cS[nt][0];
            cS[nt][1] = __expf((cS[nt][1] - m0) * scale); s0 += cS[nt][1];
            cS[nt][2] = __expf((cS[nt][2] - m1) * scale); s1 += cS[nt][2];
            cS[nt][3] = __expf((cS[nt][3] - m1) * scale); s1 += cS[nt][3];
        }
        s0 += __shfl_xor_sync(0xffffffffu, s0, 1);
        s0 += __shfl_xor_sync(0xffffffffu, s0, 2);
        s1 += __shfl_xor_sync(0xffffffffu, s1, 1);
        s1 += __shfl_xor_sync(0xffffffffu, s1, 2);
        float i0 = 1.0f / s0, i1 = 1.0f / s1;
        #pragma unroll
        for (int nt = 0; nt < 8; nt++) {
            cS[nt][0] *= i0; cS[nt][1] *= i0;
            cS[nt][2] *= i1; cS[nt][3] *= i1;
        }
    }

    uint32_t ph[4][4], pl[4][4];
    #pragma unroll
    for (int kt = 0; kt < 4; kt++) {
        #pragma unroll
        for (int half = 0; half < 2; half++) {
            int nt = 2 * kt + half;
            __nv_bfloat162 H0 = __floats2bfloat162_rn(cS[nt][0], cS[nt][1]);
            __nv_bfloat162 H1 = __floats2bfloat162_rn(cS[nt][2], cS[nt][3]);
            __nv_bfloat162 L0 = __floats2bfloat162_rn(cS[nt][0] - __bfloat162float(H0.x),
                                                      cS[nt][1] - __bfloat162float(H0.y));
            __nv_bfloat162 L1 = __floats2bfloat162_rn(cS[nt][2] - __bfloat162float(H1.x),
                                                      cS[nt][3] - __bfloat162float(H1.y));
            ph[kt][half * 2 + 0] = *(uint32_t*)&H0;
            ph[kt][half * 2 + 1] = *(uint32_t*)&H1;
            pl[kt][half * 2 + 0] = *(uint32_t*)&L0;
            pl[kt][half * 2 + 1] = *(uint32_t*)&L1;
        }
    }

    float cO[4][4];
    #pragma unroll
    for (int nt = 0; nt < 4; nt++)
        #pragma unroll
        for (int c = 0; c < 4; c++) cO[nt][c] = 0.0f;

    #pragma unroll
    for (int kt = 0; kt < 4; kt++) {
        const int vrow = kt * 16 + (lane & 15);
        uint32_t vh2[4][2], vl2[4][2];
        #pragma unroll
        for (int nt = 0; nt < 4; nt++) {
            uint32_t ad = smem_u32(&sVh[vrow][nt * 8]);
            asm volatile("ldmatrix.sync.aligned.m8n8.x2.trans.shared.b16 {%0,%1},[%2];"
                         : "=r"(vh2[nt][0]), "=r"(vh2[nt][1]) : "r"(ad));
            ad = smem_u32(&sVl[vrow][nt * 8]);
            asm volatile("ldmatrix.sync.aligned.m8n8.x2.trans.shared.b16 {%0,%1},[%2];"
                         : "=r"(vl2[nt][0]), "=r"(vl2[nt][1]) : "r"(ad));
        }
        #pragma unroll
        for (int nt = 0; nt < 4; nt++) MMA_BF16(cO[nt], ph[kt], vh2[nt]);
        #pragma unroll
        for (int nt = 0; nt < 4; nt++) MMA_BF16(cO[nt], pl[kt], vh2[nt]);
        #pragma unroll
        for (int nt = 0; nt < 4; nt++) MMA_BF16(cO[nt], ph[kt], vl2[nt]);
    }

    {
        const int g0 = lane >> 2;
        const int c2 = (lane & 3) * 2;
        #pragma unroll
        for (int half = 0; half < 2; half++) {
            int r = warp * 16 + g0 + half * 8;
            int n = ((wh * 8 + (r >> 3)) << 6) + wc * 8 + (r & 7);
            size_t base = (size_t)(b * 4096 + n) * C_DIM + head * 32;
            #pragma unroll
            for (int nt = 0; nt < 4; nt++) {
                float v0 = cO[nt][half * 2 + 0];
                float v1 = cO[nt][half * 2 + 1];
                __nv_bfloat162 H = __floats2bfloat162_rn(v0, v1);
                __nv_bfloat162 L = __floats2bfloat162_rn(v0 - __bfloat162float(H.x),
                                                         v1 - __bfloat162float(H.y));
                size_t off = base + nt * 8 + c2;
                *(__nv_bfloat162*)(oh + off) = H;
                *(__nv_bfloat162*)(ol + off) = L;
            }
        }
    }
}

// ---------------------------------------------------------------------------
// Host launcher
// ---------------------------------------------------------------------------
extern "C" void kernel_launch(void* const* d_in, const int* in_sizes, int n_in,
                              void* d_out, int out_size)
{
    const float* x      = (const float*)d_in[0];
    const float* W_qkv  = (const float*)d_in[1];
    const float* b_qkv  = (const float*)d_in[2];
    const float* W_proj = (const float*)d_in[3];
    float* out = (float*)d_out;

    float *qkv;
    __nv_bfloat16 *ah, *al, *wqh, *wql, *wph, *wpl;
    cudaGetSymbolAddress((void**)&qkv, g_qkv);
    cudaGetSymbolAddress((void**)&ah,  g_ah);
    cudaGetSymbolAddress((void**)&al,  g_al);
    cudaGetSymbolAddress((void**)&wqh, g_wqh);
    cudaGetSymbolAddress((void**)&wql, g_wql);
    cudaGetSymbolAddress((void**)&wph, g_wph);
    cudaGetSymbolAddress((void**)&wpl, g_wpl);

    cudaFuncSetAttribute(gemm3_kernel,
                         cudaFuncAttributeMaxDynamicSharedMemorySize, GEMM_DYNSMEM);
    cudaFuncSetAttribute(gemm3_qkv_kernel,
                         cudaFuncAttributeMaxDynamicSharedMemorySize, FA_DYNSMEM);

    // Weight splits only (x split fused into QKV GEMM)
    {
        int w4 = C_DIM * QKV_DIM / 4;
        split_kernel<<<(w4 + 255) / 256, 256>>>(W_qkv, wqh, wql, w4);
        int p4 = C_DIM * C_DIM / 4;
        split_kernel<<<(p4 + 255) / 256, 256>>>(W_proj, wph, wpl, p4);
    }
    // 1) QKV projection: fp32 A, in-kernel split
    {
        dim3 grid(QKV_DIM / 128, TOKENS / 128);
        gemm3_qkv_kernel<<<grid, 128, FA_DYNSMEM>>>(x, wqh, wql, b_qkv, qkv,
                                                    QKV_DIM, C_DIM);
    }
    // 2) Windowed attention
    {
        dim3 grid(1024, 12);
        attn_tc_kernel<<<grid, 128>>>(qkv, ah, al);
    }
    // 3) Output projection
    {
        dim3 grid(C_DIM / 128, TOKENS / 128);
        gemm3_kernel<<<grid, 128, GEMM_DYNSMEM>>>(ah, al, wph, wpl, nullptr, out,
                                                  C_DIM, C_DIM);
    }
}